// round 6
// baseline (speedup 1.0000x reference)
#include <cuda_runtime.h>
#include <cuda_bf16.h>
#include <cstdint>

// DecoderBlock: self-MHA (causal) -> cross-MHA (no mask).
// B=4, S=1024, D=1024, H=16, DK=64.
// All matmuls on mma.sync bf16 with hi/lo split (fp32 accum).
// R6: GEMM re-tiled to warp 64x64 (LDSM:MMA 1:6), single barrier per k-tile.

#define SEQ    1024
#define DMODEL 1024
#define NHEAD  16
#define HDIM   64
#define BATCH  4
#define MTOT   (BATCH * SEQ)   // 4096

// ---------------- scratch ----------------
__device__ __nv_bfloat16 g_qh[(size_t)MTOT * DMODEL];
__device__ __nv_bfloat16 g_ql[(size_t)MTOT * DMODEL];
__device__ __nv_bfloat16 g_kh[(size_t)MTOT * DMODEL];
__device__ __nv_bfloat16 g_kl[(size_t)MTOT * DMODEL];
__device__ __nv_bfloat16 g_vh[(size_t)MTOT * DMODEL];
__device__ __nv_bfloat16 g_vl[(size_t)MTOT * DMODEL];
__device__ __nv_bfloat16 g_ah[(size_t)MTOT * DMODEL];
__device__ __nv_bfloat16 g_al[(size_t)MTOT * DMODEL];
__device__ __nv_bfloat16 g_eh[(size_t)MTOT * DMODEL];
__device__ __nv_bfloat16 g_el[(size_t)MTOT * DMODEL];
__device__ __nv_bfloat16 g_w6h[6 * (size_t)DMODEL * DMODEL];
__device__ __nv_bfloat16 g_w6l[6 * (size_t)DMODEL * DMODEL];

// ================= PTX helpers (sm_80-level, valid on compute_103) =================
__device__ __forceinline__ uint32_t smem_u32(const void* p) {
    uint32_t a;
    asm("{ .reg .u64 t; cvta.to.shared.u64 t, %1; cvt.u32.u64 %0, t; }" : "=r"(a) : "l"(p));
    return a;
}
#define CP_ASYNC16(dst, src) asm volatile("cp.async.cg.shared.global [%0], [%1], 16;" :: "r"(dst), "l"(src))
#define CP_COMMIT()  asm volatile("cp.async.commit_group;" ::: "memory")
#define CP_WAIT2()   asm volatile("cp.async.wait_group 2;" ::: "memory")
#define CP_WAIT0()   asm volatile("cp.async.wait_group 0;" ::: "memory")

#define LDSM_X4(r0, r1, r2, r3, addr) \
    asm volatile("ldmatrix.sync.aligned.m8n8.x4.shared.b16 {%0,%1,%2,%3}, [%4];" \
                 : "=r"(r0), "=r"(r1), "=r"(r2), "=r"(r3) : "r"(addr))
#define LDSM_X4_T(r0, r1, r2, r3, addr) \
    asm volatile("ldmatrix.sync.aligned.m8n8.x4.trans.shared.b16 {%0,%1,%2,%3}, [%4];" \
                 : "=r"(r0), "=r"(r1), "=r"(r2), "=r"(r3) : "r"(addr))

#define MMA_BF16(c, a, b0v, b1v) \
    asm volatile("mma.sync.aligned.m16n8k16.row.col.f32.bf16.bf16.f32 " \
                 "{%0,%1,%2,%3}, {%4,%5,%6,%7}, {%8,%9}, {%0,%1,%2,%3};" \
                 : "+f"((c)[0]), "+f"((c)[1]), "+f"((c)[2]), "+f"((c)[3]) \
                 : "r"((a)[0]), "r"((a)[1]), "r"((a)[2]), "r"((a)[3]), \
                   "r"(b0v), "r"(b1v))

__device__ __forceinline__ void pack_split(float a, float b, uint32_t& h, uint32_t& l) {
    __nv_bfloat16 ha = __float2bfloat16(a), hb = __float2bfloat16(b);
    float ra = a - __bfloat162float(ha), rb = b - __bfloat162float(hb);
    __nv_bfloat162 hh = __halves2bfloat162(ha, hb);
    __nv_bfloat162 ll = __halves2bfloat162(__float2bfloat16(ra), __float2bfloat16(rb));
    h = *reinterpret_cast<uint32_t*>(&hh);
    l = *reinterpret_cast<uint32_t*>(&ll);
}

// ================= split fp32 -> bf16 hi/lo =================
__global__ __launch_bounds__(256) void split_kernel(const float* __restrict__ x,
                                                    __nv_bfloat16* __restrict__ hi,
                                                    __nv_bfloat16* __restrict__ lo) {
    size_t i = ((size_t)blockIdx.x * 256 + threadIdx.x) * 4;
    float4 v = *(const float4*)(x + i);
    uint32_t h0, l0, h1, l1;
    pack_split(v.x, v.y, h0, l0);
    pack_split(v.z, v.w, h1, l1);
    *(uint32_t*)(hi + i)     = h0; *(uint32_t*)(hi + i + 2) = h1;
    *(uint32_t*)(lo + i)     = l0; *(uint32_t*)(lo + i + 2) = l1;
}

// ================= fused-split mma.sync GEMM (QKV in one grid) =================
// C = A * B^T (4096x1024x1024) per z; 3 MMA passes: Ah*Bh + Ah*Bl + Al*Bh.
// CTA 128x128, 4 warps @64x64, 4-stage cp.async, pitch 40 bf16. Outputs bf16 hi/lo.
#define BM 128
#define BN 128
#define GT 128
#define TILE_BYTES (128 * 40 * 2)
#define STAGE_BYTES (4 * TILE_BYTES)
#define NK 32
#define GEMM_SMEM (4 * STAGE_BYTES)    // 163840

struct GemmTriple {
    const __nv_bfloat16* Ah[3];
    const __nv_bfloat16* Al[3];
    const __nv_bfloat16* Bh[3];
    const __nv_bfloat16* Bl[3];
    __nv_bfloat16* Ch[3];
    __nv_bfloat16* Cl[3];
};

__device__ __forceinline__ void issue_stage(uint32_t sbase,
                                            const __nv_bfloat16* Ahp, const __nv_bfloat16* Alp,
                                            const __nv_bfloat16* Bhp, const __nv_bfloat16* Blp,
                                            int kt, int tid) {
#pragma unroll
    for (int i = 0; i < 4; i++) {
        const int idx = tid + i * GT;                  // 0..511
        const int r = idx >> 2, ch = idx & 3;
        const size_t goff = (size_t)r * 1024 + (size_t)kt * 32 + ch * 8;
        const uint32_t soff = (uint32_t)(r * 80 + ch * 16);
        CP_ASYNC16(sbase + 0 * TILE_BYTES + soff, (const char*)(Ahp + goff));
        CP_ASYNC16(sbase + 1 * TILE_BYTES + soff, (const char*)(Alp + goff));
        CP_ASYNC16(sbase + 2 * TILE_BYTES + soff, (const char*)(Bhp + goff));
        CP_ASYNC16(sbase + 3 * TILE_BYTES + soff, (const char*)(Blp + goff));
    }
}

__global__ __launch_bounds__(GT, 1)
void gemm_qkv(GemmTriple P) {
    extern __shared__ char smc[];
    uint32_t sb = smem_u32(smc);
    const int tid = threadIdx.x;
    const int wid = tid >> 5, lane = tid & 31;
    const int z = blockIdx.z;
    const int m0 = blockIdx.y * BM;
    const int n0 = blockIdx.x * BN;
    const int wm = (wid & 1) * 64;
    const int wn = (wid >> 1) * 64;

    const __nv_bfloat16* Ahp = P.Ah[z] + (size_t)m0 * 1024;
    const __nv_bfloat16* Alp = P.Al[z] + (size_t)m0 * 1024;
    const __nv_bfloat16* Bhp = P.Bh[z] + (size_t)n0 * 1024;
    const __nv_bfloat16* Blp = P.Bl[z] + (size_t)n0 * 1024;

    const int lrow = (lane & 7) + ((lane >> 3) & 1) * 8;
    const int lkof = ((lane >> 4) & 1) * 8;

    float acc[4][8][4];
#pragma unroll
    for (int mt = 0; mt < 4; mt++)
#pragma unroll
        for (int nt = 0; nt < 8; nt++)
#pragma unroll
            for (int q = 0; q < 4; q++) acc[mt][nt][q] = 0.f;

#pragma unroll
    for (int s = 0; s < 3; s++) {
        issue_stage(sb + s * STAGE_BYTES, Ahp, Alp, Bhp, Blp, s, tid);
        CP_COMMIT();
    }

    for (int kt = 0; kt < NK; kt++) {
        CP_WAIT2();
        __syncthreads();   // all warps done reading buffer (kt-1)&3, which kt+3 overwrites
        if (kt + 3 < NK)
            issue_stage(sb + ((kt + 3) & 3) * STAGE_BYTES, Ahp, Alp, Bhp, Blp, kt + 3, tid);
        CP_COMMIT();

        const uint32_t stb = sb + (kt & 3) * STAGE_BYTES;
#pragma unroll
        for (int ks = 0; ks < 2; ks++) {
            const uint32_t koff = (uint32_t)((ks * 16 + lkof) * 2);
            uint32_t ah[4][4], al[4][4];
#pragma unroll
            for (int mt = 0; mt < 4; mt++) {
                uint32_t ro = (uint32_t)((wm + mt * 16 + lrow) * 80) + koff;
                LDSM_X4(ah[mt][0], ah[mt][1], ah[mt][2], ah[mt][3], stb + ro);
                LDSM_X4(al[mt][0], al[mt][1], al[mt][2], al[mt][3], stb + TILE_BYTES + ro);
            }
#pragma unroll
            for (int g = 0; g < 4; g++) {   // 16 B-cols per g -> nt = 2g, 2g+1
                uint32_t ro = (uint32_t)((wn + g * 16 + lrow) * 80) + koff;
                uint32_t h0, h1, h2, h3, l0, l1, l2, l3;
                LDSM_X4(h0, h1, h2, h3, stb + 2 * TILE_BYTES + ro);
                LDSM_X4(l0, l1, l2, l3, stb + 3 * TILE_BYTES + ro);
#pragma unroll
                for (int mt = 0; mt < 4; mt++) {
                    MMA_BF16(acc[mt][2 * g + 0], ah[mt], h0, h2);
                    MMA_BF16(acc[mt][2 * g + 0], ah[mt], l0, l2);
                    MMA_BF16(acc[mt][2 * g + 0], al[mt], h0, h2);
                    MMA_BF16(acc[mt][2 * g + 1], ah[mt], h1, h3);
                    MMA_BF16(acc[mt][2 * g + 1], ah[mt], l1, l3);
                    MMA_BF16(acc[mt][2 * g + 1], al[mt], h1, h3);
                }
            }
        }
    }

    __nv_bfloat16* Ch = P.Ch[z];
    __nv_bfloat16* Cl = P.Cl[z];
#pragma unroll
    for (int mt = 0; mt < 4; mt++) {
#pragma unroll
        for (int nt = 0; nt < 8; nt++) {
            int row = m0 + wm + mt * 16 + (lane >> 2);
            int col = n0 + wn + nt * 8 + (lane & 3) * 2;
            uint32_t h01, l01, h23, l23;
            pack_split(acc[mt][nt][0], acc[mt][nt][1], h01, l01);
            pack_split(acc[mt][nt][2], acc[mt][nt][3], h23, l23);
            *(uint32_t*)(Ch + (size_t)row * 1024 + col) = h01;
            *(uint32_t*)(Cl + (size_t)row * 1024 + col) = l01;
            *(uint32_t*)(Ch + (size_t)(row + 8) * 1024 + col) = h23;
            *(uint32_t*)(Cl + (size_t)(row + 8) * 1024 + col) = l23;
        }
    }
}

// ================= tensor-core flash attention (bf16 split, fp32 softmax) =================
// CTA: 64 queries, 4 warps (m16 each), full n64 per warp. grid (16, H, B), 128 thr.
#define APITCH 72
#define ATILE_B (64 * APITCH * 2)     // 9216
#define AQ_H 0
#define AQ_L ATILE_B
#define AST(s, t) (2 * ATILE_B + (s) * (4 * ATILE_B) + (t) * ATILE_B)
#define ATTN_SMEM (2 * ATILE_B + 2 * 4 * ATILE_B)   // 92160

__device__ __forceinline__ void attn_load_tile(uint32_t dst, const __nv_bfloat16* src, int tid) {
#pragma unroll
    for (int i = 0; i < 4; i++) {
        int idx = tid + i * 128;
        int r = idx >> 3, c = idx & 7;
        CP_ASYNC16(dst + (uint32_t)(r * 144 + c * 16),
                   (const char*)(src + (size_t)r * 1024 + c * 8));
    }
}

__global__ __launch_bounds__(128, 2)
void attn_mma(const __nv_bfloat16* __restrict__ Qh, const __nv_bfloat16* __restrict__ Ql,
              const __nv_bfloat16* __restrict__ Kh, const __nv_bfloat16* __restrict__ Kl,
              const __nv_bfloat16* __restrict__ Vh, const __nv_bfloat16* __restrict__ Vl,
              float* __restrict__ Of,
              __nv_bfloat16* __restrict__ Oh, __nv_bfloat16* __restrict__ Ol,
              int causal) {
    extern __shared__ char smc[];
    uint32_t sb = smem_u32(smc);
    const int tid = threadIdx.x;
    const int wid = tid >> 5, lane = tid & 31;
    const int q0 = blockIdx.x * 64;
    const int h = blockIdx.y, b = blockIdx.z;
    const size_t rowbase = (size_t)(b * SEQ);
    const int colbase = h * HDIM;

    const int lrow = (lane & 7) + ((lane >> 3) & 1) * 8;
    const int lkof = ((lane >> 4) & 1) * 8;
    const int vrow_l = (lane & 7) + ((lane >> 4) & 1) * 8;
    const int vcol_l = ((lane >> 3) & 1) * 8;

    attn_load_tile(sb + AQ_H, Qh + (rowbase + q0) * 1024 + colbase, tid);
    attn_load_tile(sb + AQ_L, Ql + (rowbase + q0) * 1024 + colbase, tid);
    attn_load_tile(sb + AST(0, 0), Kh + rowbase * 1024 + colbase, tid);
    attn_load_tile(sb + AST(0, 1), Kl + rowbase * 1024 + colbase, tid);
    attn_load_tile(sb + AST(0, 2), Vh + rowbase * 1024 + colbase, tid);
    attn_load_tile(sb + AST(0, 3), Vl + rowbase * 1024 + colbase, tid);
    CP_COMMIT();

    const int njt = causal ? (blockIdx.x + 1) : (SEQ / 64);

    uint32_t qhf[4][4], qlf[4][4];
    float o[8][4];
#pragma unroll
    for (int nt = 0; nt < 8; nt++)
#pragma unroll
        for (int q = 0; q < 4; q++) o[nt][q] = 0.f;
    float m_[2] = {-1e30f, -1e30f}, l_[2] = {0.f, 0.f};

    for (int j = 0; j < njt; j++) {
        CP_WAIT0();
        __syncthreads();
        if (j + 1 < njt) {
            const size_t kb = (rowbase + (size_t)(j + 1) * 64) * 1024 + colbase;
            const int s = (j + 1) & 1;
            attn_load_tile(sb + AST(s, 0), Kh + kb, tid);
            attn_load_tile(sb + AST(s, 1), Kl + kb, tid);
            attn_load_tile(sb + AST(s, 2), Vh + kb, tid);
            attn_load_tile(sb + AST(s, 3), Vl + kb, tid);
            CP_COMMIT();
        }
        if (j == 0) {
#pragma unroll
            for (int kt = 0; kt < 4; kt++) {
                uint32_t ro = (uint32_t)((wid * 16 + lrow) * 144 + (kt * 16 + lkof) * 2);
                LDSM_X4(qhf[kt][0], qhf[kt][1], qhf[kt][2], qhf[kt][3], sb + AQ_H + ro);
                LDSM_X4(qlf[kt][0], qlf[kt][1], qlf[kt][2], qlf[kt][3], sb + AQ_L + ro);
            }
        }

        const uint32_t khb = sb + AST(j & 1, 0);
        const uint32_t klb = sb + AST(j & 1, 1);
        const uint32_t vhb = sb + AST(j & 1, 2);
        const uint32_t vlb = sb + AST(j & 1, 3);

        float s[8][4];
#pragma unroll
        for (int nt = 0; nt < 8; nt++)
#pragma unroll
            for (int q = 0; q < 4; q++) s[nt][q] = 0.f;
#pragma unroll
        for (int kt = 0; kt < 4; kt++) {
            uint32_t bh[8][2], bl[8][2];
#pragma unroll
            for (int g = 0; g < 4; g++) {
                uint32_t ro = (uint32_t)((g * 16 + lrow) * 144 + (kt * 16 + lkof) * 2);
                uint32_t r0, r1, r2, r3;
                LDSM_X4(r0, r1, r2, r3, khb + ro);
                bh[2 * g + 0][0] = r0; bh[2 * g + 0][1] = r2;
                bh[2 * g + 1][0] = r1; bh[2 * g + 1][1] = r3;
                LDSM_X4(r0, r1, r2, r3, klb + ro);
                bl[2 * g + 0][0] = r0; bl[2 * g + 0][1] = r2;
                bl[2 * g + 1][0] = r1; bl[2 * g + 1][1] = r3;
            }
#pragma unroll
            for (int nt = 0; nt < 8; nt++) {
                MMA_BF16(s[nt], qhf[kt], bh[nt][0], bh[nt][1]);
                MMA_BF16(s[nt], qhf[kt], bl[nt][0], bl[nt][1]);
                MMA_BF16(s[nt], qlf[kt], bh[nt][0], bh[nt][1]);
            }
        }

#pragma unroll
        for (int nt = 0; nt < 8; nt++)
#pragma unroll
            for (int q = 0; q < 4; q++) s[nt][q] *= 0.125f;
        if (causal && j == njt - 1) {
            const int r0l = wid * 16 + (lane >> 2), r1l = r0l + 8;
#pragma unroll
            for (int nt = 0; nt < 8; nt++) {
                const int c0 = nt * 8 + (lane & 3) * 2;
                if (c0 > r0l)     s[nt][0] = -1e9f;
                if (c0 + 1 > r0l) s[nt][1] = -1e9f;
                if (c0 > r1l)     s[nt][2] = -1e9f;
                if (c0 + 1 > r1l) s[nt][3] = -1e9f;
            }
        }

        float mx0 = -1e30f, mx1 = -1e30f;
#pragma unroll
        for (int nt = 0; nt < 8; nt++) {
            mx0 = fmaxf(mx0, fmaxf(s[nt][0], s[nt][1]));
            mx1 = fmaxf(mx1, fmaxf(s[nt][2], s[nt][3]));
        }
        mx0 = fmaxf(mx0, __shfl_xor_sync(0xffffffffu, mx0, 1));
        mx0 = fmaxf(mx0, __shfl_xor_sync(0xffffffffu, mx0, 2));
        mx1 = fmaxf(mx1, __shfl_xor_sync(0xffffffffu, mx1, 1));
        mx1 = fmaxf(mx1, __shfl_xor_sync(0xffffffffu, mx1, 2));
        const float mn0 = fmaxf(m_[0], mx0), mn1 = fmaxf(m_[1], mx1);
        const float f0 = __expf(m_[0] - mn0), f1 = __expf(m_[1] - mn1);
        m_[0] = mn0; m_[1] = mn1;
        float rs0 = 0.f, rs1 = 0.f;
#pragma unroll
        for (int nt = 0; nt < 8; nt++) {
            s[nt][0] = __expf(s[nt][0] - mn0);
            s[nt][1] = __expf(s[nt][1] - mn0);
            s[nt][2] = __expf(s[nt][2] - mn1);
            s[nt][3] = __expf(s[nt][3] - mn1);
            rs0 += s[nt][0] + s[nt][1];
            rs1 += s[nt][2] + s[nt][3];
        }
        rs0 += __shfl_xor_sync(0xffffffffu, rs0, 1);
        rs0 += __shfl_xor_sync(0xffffffffu, rs0, 2);
        rs1 += __shfl_xor_sync(0xffffffffu, rs1, 1);
        rs1 += __shfl_xor_sync(0xffffffffu, rs1, 2);
        l_[0] = l_[0] * f0 + rs0;
        l_[1] = l_[1] * f1 + rs1;
#pragma unroll
        for (int nt = 0; nt < 8; nt++) {
            o[nt][0] *= f0; o[nt][1] *= f0; o[nt][2] *= f1; o[nt][3] *= f1;
        }

        uint32_t ph[4][4], pl[4][4];
#pragma unroll
        for (int kt = 0; kt < 4; kt++) {
            pack_split(s[2 * kt][0],     s[2 * kt][1],     ph[kt][0], pl[kt][0]);
            pack_split(s[2 * kt][2],     s[2 * kt][3],     ph[kt][1], pl[kt][1]);
            pack_split(s[2 * kt + 1][0], s[2 * kt + 1][1], ph[kt][2], pl[kt][2]);
            pack_split(s[2 * kt + 1][2], s[2 * kt + 1][3], ph[kt][3], pl[kt][3]);
        }

#pragma unroll
        for (int kt = 0; kt < 4; kt++) {
            const uint32_t vro = (uint32_t)((kt * 16 + vrow_l) * 144);
            uint32_t bh[8][2], bl[8][2];
#pragma unroll
            for (int g = 0; g < 4; g++) {
                uint32_t ro = vro + (uint32_t)((g * 16 + vcol_l) * 2);
                uint32_t r0, r1, r2, r3;
                LDSM_X4_T(r0, r1, r2, r3, vhb + ro);
                bh[2 * g + 0][0] = r0; bh[2 * g + 0][1] = r2;
                bh[2 * g + 1][0] = r1; bh[2 * g + 1][1] = r3;
                LDSM_X4_T(r0, r1, r2, r3, vlb + ro);
                bl[2 * g + 0][0] = r0; bl[2 * g + 0][1] = r2;
                bl[2 * g + 1][0] = r1; bl[2 * g + 1][1] = r3;
            }
#pragma unroll
            for (int nt = 0; nt < 8; nt++) {
                MMA_BF16(o[nt], ph[kt], bh[nt][0], bh[nt][1]);
                MMA_BF16(o[nt], ph[kt], bl[nt][0], bl[nt][1]);
                MMA_BF16(o[nt], pl[kt], bh[nt][0], bh[nt][1]);
            }
        }
    }

    const float inv0 = 1.f / l_[0], inv1 = 1.f / l_[1];
    const size_t row0 = rowbase + q0 + wid * 16 + (lane >> 2);
    const int col = colbase + (lane & 3) * 2;
    if (Of) {
#pragma unroll
        for (int nt = 0; nt < 8; nt++) {
            *(float2*)(Of + row0 * 1024 + col + nt * 8) =
                make_float2(o[nt][0] * inv0, o[nt][1] * inv0);
            *(float2*)(Of + (row0 + 8) * 1024 + col + nt * 8) =
                make_float2(o[nt][2] * inv1, o[nt][3] * inv1);
        }
    } else {
#pragma unroll
        for (int nt = 0; nt < 8; nt++) {
            uint32_t h01, l01, h23, l23;
            pack_split(o[nt][0] * inv0, o[nt][1] * inv0, h01, l01);
            pack_split(o[nt][2] * inv1, o[nt][3] * inv1, h23, l23);
            *(uint32_t*)(Oh + row0 * 1024 + col + nt * 8) = h01;
            *(uint32_t*)(Ol + row0 * 1024 + col + nt * 8) = l01;
            *(uint32_t*)(Oh + (row0 + 8) * 1024 + col + nt * 8) = h23;
            *(uint32_t*)(Ol + (row0 + 8) * 1024 + col + nt * 8) = l23;
        }
    }
}

// ================= launch =================
extern "C" void kernel_launch(void* const* d_in, const int* in_sizes, int n_in,
                              void* d_out, int out_size) {
    const float* x   = (const float*)d_in[0];
    const float* enc = (const float*)d_in[1];
    const float* w[6] = {(const float*)d_in[4], (const float*)d_in[5],
                         (const float*)d_in[6], (const float*)d_in[7],
                         (const float*)d_in[8], (const float*)d_in[9]};
    float* out = (float*)d_out;

    __nv_bfloat16 *qh, *ql, *kh, *kl, *vh, *vl, *ah, *al, *eh, *el, *wh, *wl;
    cudaGetSymbolAddress((void**)&qh, g_qh);
    cudaGetSymbolAddress((void**)&ql, g_ql);
    cudaGetSymbolAddress((void**)&kh, g_kh);
    cudaGetSymbolAddress((void**)&kl, g_kl);
    cudaGetSymbolAddress((void**)&vh, g_vh);
    cudaGetSymbolAddress((void**)&vl, g_vl);
    cudaGetSymbolAddress((void**)&ah, g_ah);
    cudaGetSymbolAddress((void**)&al, g_al);
    cudaGetSymbolAddress((void**)&eh, g_eh);
    cudaGetSymbolAddress((void**)&el, g_el);
    cudaGetSymbolAddress((void**)&wh, g_w6h);
    cudaGetSymbolAddress((void**)&wl, g_w6l);

    cudaFuncSetAttribute(gemm_qkv, cudaFuncAttributeMaxDynamicSharedMemorySize, GEMM_SMEM);
    cudaFuncSetAttribute(attn_mma, cudaFuncAttributeMaxDynamicSharedMemorySize, ATTN_SMEM);

    const size_t WSZ = (size_t)DMODEL * DMODEL;
    const int actBlocks = (MTOT * DMODEL) / (256 * 4);   // 4096
    const int wBlocks   = (int)(WSZ / (256 * 4));        // 1024
    dim3 gg(DMODEL / BN, MTOT / BM, 3);                  // (8, 32, 3)
    dim3 ga(SEQ / 64, NHEAD, BATCH);                     // (16, 16, 4)

    split_kernel<<<actBlocks, 256>>>(x, ah, al);
    split_kernel<<<actBlocks, 256>>>(enc, eh, el);
    for (int i = 0; i < 6; i++)
        split_kernel<<<wBlocks, 256>>>(w[i], wh + i * WSZ, wl + i * WSZ);

    // ---- self-attention block ----
    GemmTriple Ps;
    for (int zi = 0; zi < 3; zi++) {
        Ps.Ah[zi] = ah; Ps.Al[zi] = al;
        Ps.Bh[zi] = wh + zi * WSZ; Ps.Bl[zi] = wl + zi * WSZ;
    }
    Ps.Ch[0] = qh; Ps.Cl[0] = ql;
    Ps.Ch[1] = kh; Ps.Cl[1] = kl;
    Ps.Ch[2] = vh; Ps.Cl[2] = vl;
    gemm_qkv<<<gg, GT, GEMM_SMEM>>>(Ps);
    attn_mma<<<ga, 128, ATTN_SMEM>>>(qh, ql, kh, kl, vh, vl, nullptr, ah, al, 1);

    // ---- cross-attention block ----
    GemmTriple Pc;
    Pc.Ah[0] = ah; Pc.Al[0] = al;
    Pc.Ah[1] = eh; Pc.Al[1] = el;
    Pc.Ah[2] = eh; Pc.Al[2] = el;
    for (int zi = 0; zi < 3; zi++) {
        Pc.Bh[zi] = wh + (3 + zi) * WSZ; Pc.Bl[zi] = wl + (3 + zi) * WSZ;
    }
    Pc.Ch[0] = qh; Pc.Cl[0] = ql;
    Pc.Ch[1] = kh; Pc.Cl[1] = kl;
    Pc.Ch[2] = vh; Pc.Cl[2] = vl;
    gemm_qkv<<<gg, GT, GEMM_SMEM>>>(Pc);
    attn_mma<<<ga, 128, ATTN_SMEM>>>(qh, ql, kh, kl, vh, vl, out, nullptr, nullptr, 0);
}

// round 8
// speedup vs baseline: 1.1179x; 1.1179x over previous
#include <cuda_runtime.h>
#include <cuda_bf16.h>
#include <cstdint>

// DecoderBlock: self-MHA (causal) -> cross-MHA (no mask).
// B=4, S=1024, D=1024, H=16, DK=64.
// All matmuls mma.sync bf16 hi/lo split (fp32 accum).
// R8: GEMM 8 warps @64x32, 2-stage pipeline (80KB smem) -> 2 CTAs/SM. (R7 + compile fix)

#define SEQ    1024
#define DMODEL 1024
#define NHEAD  16
#define HDIM   64
#define BATCH  4
#define MTOT   (BATCH * SEQ)   // 4096

// ---------------- scratch ----------------
__device__ __nv_bfloat16 g_qh[(size_t)MTOT * DMODEL];
__device__ __nv_bfloat16 g_ql[(size_t)MTOT * DMODEL];
__device__ __nv_bfloat16 g_kh[(size_t)MTOT * DMODEL];
__device__ __nv_bfloat16 g_kl[(size_t)MTOT * DMODEL];
__device__ __nv_bfloat16 g_vh[(size_t)MTOT * DMODEL];
__device__ __nv_bfloat16 g_vl[(size_t)MTOT * DMODEL];
__device__ __nv_bfloat16 g_ah[(size_t)MTOT * DMODEL];
__device__ __nv_bfloat16 g_al[(size_t)MTOT * DMODEL];
__device__ __nv_bfloat16 g_eh[(size_t)MTOT * DMODEL];
__device__ __nv_bfloat16 g_el[(size_t)MTOT * DMODEL];
__device__ __nv_bfloat16 g_w6h[6 * (size_t)DMODEL * DMODEL];
__device__ __nv_bfloat16 g_w6l[6 * (size_t)DMODEL * DMODEL];

// ================= PTX helpers =================
__device__ __forceinline__ uint32_t smem_u32(const void* p) {
    uint32_t a;
    asm("{ .reg .u64 t; cvta.to.shared.u64 t, %1; cvt.u32.u64 %0, t; }" : "=r"(a) : "l"(p));
    return a;
}
#define CP_ASYNC16(dst, src) asm volatile("cp.async.cg.shared.global [%0], [%1], 16;" :: "r"(dst), "l"(src))
#define CP_COMMIT()  asm volatile("cp.async.commit_group;" ::: "memory")
#define CP_WAIT1()   asm volatile("cp.async.wait_group 1;" ::: "memory")
#define CP_WAIT0()   asm volatile("cp.async.wait_group 0;" ::: "memory")

#define LDSM_X4(r0, r1, r2, r3, addr) \
    asm volatile("ldmatrix.sync.aligned.m8n8.x4.shared.b16 {%0,%1,%2,%3}, [%4];" \
                 : "=r"(r0), "=r"(r1), "=r"(r2), "=r"(r3) : "r"(addr))
#define LDSM_X4_T(r0, r1, r2, r3, addr) \
    asm volatile("ldmatrix.sync.aligned.m8n8.x4.trans.shared.b16 {%0,%1,%2,%3}, [%4];" \
                 : "=r"(r0), "=r"(r1), "=r"(r2), "=r"(r3) : "r"(addr))

#define MMA_BF16(c, a, b0v, b1v) \
    asm volatile("mma.sync.aligned.m16n8k16.row.col.f32.bf16.bf16.f32 " \
                 "{%0,%1,%2,%3}, {%4,%5,%6,%7}, {%8,%9}, {%0,%1,%2,%3};" \
                 : "+f"((c)[0]), "+f"((c)[1]), "+f"((c)[2]), "+f"((c)[3]) \
                 : "r"((a)[0]), "r"((a)[1]), "r"((a)[2]), "r"((a)[3]), \
                   "r"(b0v), "r"(b1v))

__device__ __forceinline__ void pack_split(float a, float b, uint32_t& h, uint32_t& l) {
    __nv_bfloat16 ha = __float2bfloat16(a), hb = __float2bfloat16(b);
    float ra = a - __bfloat162float(ha), rb = b - __bfloat162float(hb);
    __nv_bfloat162 hh = __halves2bfloat162(ha, hb);
    __nv_bfloat162 ll = __halves2bfloat162(__float2bfloat16(ra), __float2bfloat16(rb));
    h = *reinterpret_cast<uint32_t*>(&hh);
    l = *reinterpret_cast<uint32_t*>(&ll);
}

// ================= split fp32 -> bf16 hi/lo =================
__global__ __launch_bounds__(256) void split_kernel(const float* __restrict__ x,
                                                    __nv_bfloat16* __restrict__ hi,
                                                    __nv_bfloat16* __restrict__ lo) {
    size_t i = ((size_t)blockIdx.x * 256 + threadIdx.x) * 4;
    float4 v = *(const float4*)(x + i);
    uint32_t h0, l0, h1, l1;
    pack_split(v.x, v.y, h0, l0);
    pack_split(v.z, v.w, h1, l1);
    *(uint32_t*)(hi + i)     = h0; *(uint32_t*)(hi + i + 2) = h1;
    *(uint32_t*)(lo + i)     = l0; *(uint32_t*)(lo + i + 2) = l1;
}

// ================= fused-split mma.sync GEMM (QKV in one grid) =================
// C = A * B^T (4096x1024x1024) per z; 3 MMA passes: Ah*Bh + Ah*Bl + Al*Bh.
// CTA 128x128, 8 warps @64x32, 2-stage cp.async (80KB) -> 2 CTAs/SM.
#define BM 128
#define BN 128
#define GT 256
#define TILE_BYTES (128 * 40 * 2)
#define STAGE_BYTES (4 * TILE_BYTES)   // Ah, Al, Bh, Bl
#define NK 32
#define GEMM_SMEM (2 * STAGE_BYTES)    // 81920

struct GemmTriple {
    const __nv_bfloat16* Ah[3];
    const __nv_bfloat16* Al[3];
    const __nv_bfloat16* Bh[3];
    const __nv_bfloat16* Bl[3];
    __nv_bfloat16* Ch[3];
    __nv_bfloat16* Cl[3];
};

__device__ __forceinline__ void issue_stage(uint32_t sbase,
                                            const __nv_bfloat16* Ahp, const __nv_bfloat16* Alp,
                                            const __nv_bfloat16* Bhp, const __nv_bfloat16* Blp,
                                            int kt, int tid) {
#pragma unroll
    for (int i = 0; i < 2; i++) {
        const int idx = tid + i * GT;                  // 0..511
        const int r = idx >> 2, ch = idx & 3;
        const size_t goff = (size_t)r * 1024 + (size_t)kt * 32 + ch * 8;
        const uint32_t soff = (uint32_t)(r * 80 + ch * 16);
        CP_ASYNC16(sbase + 0 * TILE_BYTES + soff, (const char*)(Ahp + goff));
        CP_ASYNC16(sbase + 1 * TILE_BYTES + soff, (const char*)(Alp + goff));
        CP_ASYNC16(sbase + 2 * TILE_BYTES + soff, (const char*)(Bhp + goff));
        CP_ASYNC16(sbase + 3 * TILE_BYTES + soff, (const char*)(Blp + goff));
    }
}

__global__ __launch_bounds__(GT, 2)
void gemm_qkv(GemmTriple P) {
    extern __shared__ char smc[];
    uint32_t sb = smem_u32(smc);
    const int tid = threadIdx.x;
    const int wid = tid >> 5, lane = tid & 31;
    const int z = blockIdx.z;
    const int m0 = blockIdx.y * BM;
    const int n0 = blockIdx.x * BN;
    const int wm = (wid & 1) * 64;
    const int wn = (wid >> 1) * 32;

    const __nv_bfloat16* Ahp = P.Ah[z] + (size_t)m0 * 1024;
    const __nv_bfloat16* Alp = P.Al[z] + (size_t)m0 * 1024;
    const __nv_bfloat16* Bhp = P.Bh[z] + (size_t)n0 * 1024;
    const __nv_bfloat16* Blp = P.Bl[z] + (size_t)n0 * 1024;

    const int lrow = (lane & 7) + ((lane >> 3) & 1) * 8;
    const int lkof = ((lane >> 4) & 1) * 8;

    float acc[4][4][4];
#pragma unroll
    for (int mt = 0; mt < 4; mt++)
#pragma unroll
        for (int nt = 0; nt < 4; nt++)
#pragma unroll
            for (int q = 0; q < 4; q++) acc[mt][nt][q] = 0.f;

    issue_stage(sb, Ahp, Alp, Bhp, Blp, 0, tid);
    CP_COMMIT();
    issue_stage(sb + STAGE_BYTES, Ahp, Alp, Bhp, Blp, 1, tid);
    CP_COMMIT();

    for (int kt = 0; kt < NK; kt++) {
        CP_WAIT1();            // stage kt arrived
        __syncthreads();

        const uint32_t stb = sb + (kt & 1) * STAGE_BYTES;
#pragma unroll
        for (int ks = 0; ks < 2; ks++) {
            const uint32_t koff = (uint32_t)((ks * 16 + lkof) * 2);
            uint32_t ah[4][4], al[4][4];
#pragma unroll
            for (int mt = 0; mt < 4; mt++) {
                uint32_t ro = (uint32_t)((wm + mt * 16 + lrow) * 80) + koff;
                LDSM_X4(ah[mt][0], ah[mt][1], ah[mt][2], ah[mt][3], stb + ro);
                LDSM_X4(al[mt][0], al[mt][1], al[mt][2], al[mt][3], stb + TILE_BYTES + ro);
            }
#pragma unroll
            for (int g = 0; g < 2; g++) {   // two 16-col B groups -> nt = 2g, 2g+1
                uint32_t ro = (uint32_t)((wn + g * 16 + lrow) * 80) + koff;
                uint32_t h0, h1, h2, h3, l0, l1, l2, l3;
                LDSM_X4(h0, h1, h2, h3, stb + 2 * TILE_BYTES + ro);
                LDSM_X4(l0, l1, l2, l3, stb + 3 * TILE_BYTES + ro);
#pragma unroll
                for (int mt = 0; mt < 4; mt++) {
                    MMA_BF16(acc[mt][2 * g + 0], ah[mt], h0, h2);
                    MMA_BF16(acc[mt][2 * g + 0], ah[mt], l0, l2);
                    MMA_BF16(acc[mt][2 * g + 0], al[mt], h0, h2);
                    MMA_BF16(acc[mt][2 * g + 1], ah[mt], h1, h3);
                    MMA_BF16(acc[mt][2 * g + 1], ah[mt], l1, l3);
                    MMA_BF16(acc[mt][2 * g + 1], al[mt], h1, h3);
                }
            }
        }
        __syncthreads();       // all warps done with buffer kt&1
        if (kt + 2 < NK)
            issue_stage(stb, Ahp, Alp, Bhp, Blp, kt + 2, tid);
        CP_COMMIT();
    }

    __nv_bfloat16* Ch = P.Ch[z];
    __nv_bfloat16* Cl = P.Cl[z];
#pragma unroll
    for (int mt = 0; mt < 4; mt++) {
#pragma unroll
        for (int nt = 0; nt < 4; nt++) {
            int row = m0 + wm + mt * 16 + (lane >> 2);
            int col = n0 + wn + nt * 8 + (lane & 3) * 2;
            uint32_t h01, l01, h23, l23;
            pack_split(acc[mt][nt][0], acc[mt][nt][1], h01, l01);
            pack_split(acc[mt][nt][2], acc[mt][nt][3], h23, l23);
            *(uint32_t*)(Ch + (size_t)row * 1024 + col) = h01;
            *(uint32_t*)(Cl + (size_t)row * 1024 + col) = l01;
            *(uint32_t*)(Ch + (size_t)(row + 8) * 1024 + col) = h23;
            *(uint32_t*)(Cl + (size_t)(row + 8) * 1024 + col) = l23;
        }
    }
}

// ================= tensor-core flash attention (bf16 split, fp32 softmax) =================
#define APITCH 72
#define ATILE_B (64 * APITCH * 2)     // 9216
#define AQ_H 0
#define AQ_L ATILE_B
#define AST(s, t) (2 * ATILE_B + (s) * (4 * ATILE_B) + (t) * ATILE_B)
#define ATTN_SMEM (2 * ATILE_B + 2 * 4 * ATILE_B)   // 92160

__device__ __forceinline__ void attn_load_tile(uint32_t dst, const __nv_bfloat16* src, int tid) {
#pragma unroll
    for (int i = 0; i < 4; i++) {
        int idx = tid + i * 128;
        int r = idx >> 3, c = idx & 7;
        CP_ASYNC16(dst + (uint32_t)(r * 144 + c * 16),
                   (const char*)(src + (size_t)r * 1024 + c * 8));
    }
}

__global__ __launch_bounds__(128, 2)
void attn_mma(const __nv_bfloat16* __restrict__ Qh, const __nv_bfloat16* __restrict__ Ql,
              const __nv_bfloat16* __restrict__ Kh, const __nv_bfloat16* __restrict__ Kl,
              const __nv_bfloat16* __restrict__ Vh, const __nv_bfloat16* __restrict__ Vl,
              float* __restrict__ Of,
              __nv_bfloat16* __restrict__ Oh, __nv_bfloat16* __restrict__ Ol,
              int causal) {
    extern __shared__ char smc[];
    uint32_t sb = smem_u32(smc);
    const int tid = threadIdx.x;
    const int wid = tid >> 5, lane = tid & 31;
    const int q0 = blockIdx.x * 64;
    const int h = blockIdx.y, b = blockIdx.z;
    const size_t rowbase = (size_t)(b * SEQ);
    const int colbase = h * HDIM;

    const int lrow = (lane & 7) + ((lane >> 3) & 1) * 8;
    const int lkof = ((lane >> 4) & 1) * 8;
    const int vrow_l = (lane & 7) + ((lane >> 4) & 1) * 8;
    const int vcol_l = ((lane >> 3) & 1) * 8;

    attn_load_tile(sb + AQ_H, Qh + (rowbase + q0) * 1024 + colbase, tid);
    attn_load_tile(sb + AQ_L, Ql + (rowbase + q0) * 1024 + colbase, tid);
    attn_load_tile(sb + AST(0, 0), Kh + rowbase * 1024 + colbase, tid);
    attn_load_tile(sb + AST(0, 1), Kl + rowbase * 1024 + colbase, tid);
    attn_load_tile(sb + AST(0, 2), Vh + rowbase * 1024 + colbase, tid);
    attn_load_tile(sb + AST(0, 3), Vl + rowbase * 1024 + colbase, tid);
    CP_COMMIT();

    const int njt = causal ? (blockIdx.x + 1) : (SEQ / 64);

    uint32_t qhf[4][4], qlf[4][4];
    float o[8][4];
#pragma unroll
    for (int nt = 0; nt < 8; nt++)
#pragma unroll
        for (int q = 0; q < 4; q++) o[nt][q] = 0.f;
    float m_[2] = {-1e30f, -1e30f}, l_[2] = {0.f, 0.f};

    for (int j = 0; j < njt; j++) {
        CP_WAIT0();
        __syncthreads();
        if (j + 1 < njt) {
            const size_t kb = (rowbase + (size_t)(j + 1) * 64) * 1024 + colbase;
            const int s = (j + 1) & 1;
            attn_load_tile(sb + AST(s, 0), Kh + kb, tid);
            attn_load_tile(sb + AST(s, 1), Kl + kb, tid);
            attn_load_tile(sb + AST(s, 2), Vh + kb, tid);
            attn_load_tile(sb + AST(s, 3), Vl + kb, tid);
            CP_COMMIT();
        }
        if (j == 0) {
#pragma unroll
            for (int kt = 0; kt < 4; kt++) {
                uint32_t ro = (uint32_t)((wid * 16 + lrow) * 144 + (kt * 16 + lkof) * 2);
                LDSM_X4(qhf[kt][0], qhf[kt][1], qhf[kt][2], qhf[kt][3], sb + AQ_H + ro);
                LDSM_X4(qlf[kt][0], qlf[kt][1], qlf[kt][2], qlf[kt][3], sb + AQ_L + ro);
            }
        }

        const uint32_t khb = sb + AST(j & 1, 0);
        const uint32_t klb = sb + AST(j & 1, 1);
        const uint32_t vhb = sb + AST(j & 1, 2);
        const uint32_t vlb = sb + AST(j & 1, 3);

        float s[8][4];
#pragma unroll
        for (int nt = 0; nt < 8; nt++)
#pragma unroll
            for (int q = 0; q < 4; q++) s[nt][q] = 0.f;
#pragma unroll
        for (int kt = 0; kt < 4; kt++) {
            uint32_t bh[8][2], bl[8][2];
#pragma unroll
            for (int g = 0; g < 4; g++) {
                uint32_t ro = (uint32_t)((g * 16 + lrow) * 144 + (kt * 16 + lkof) * 2);
                uint32_t r0, r1, r2, r3;
                LDSM_X4(r0, r1, r2, r3, khb + ro);
                bh[2 * g + 0][0] = r0; bh[2 * g + 0][1] = r2;
                bh[2 * g + 1][0] = r1; bh[2 * g + 1][1] = r3;
                LDSM_X4(r0, r1, r2, r3, klb + ro);
                bl[2 * g + 0][0] = r0; bl[2 * g + 0][1] = r2;
                bl[2 * g + 1][0] = r1; bl[2 * g + 1][1] = r3;
            }
#pragma unroll
            for (int nt = 0; nt < 8; nt++) {
                MMA_BF16(s[nt], qhf[kt], bh[nt][0], bh[nt][1]);
                MMA_BF16(s[nt], qhf[kt], bl[nt][0], bl[nt][1]);
                MMA_BF16(s[nt], qlf[kt], bh[nt][0], bh[nt][1]);
            }
        }

#pragma unroll
        for (int nt = 0; nt < 8; nt++)
#pragma unroll
            for (int q = 0; q < 4; q++) s[nt][q] *= 0.125f;
        if (causal && j == njt - 1) {
            const int r0l = wid * 16 + (lane >> 2), r1l = r0l + 8;
#pragma unroll
            for (int nt = 0; nt < 8; nt++) {
                const int c0 = nt * 8 + (lane & 3) * 2;
                if (c0 > r0l)     s[nt][0] = -1e9f;
                if (c0 + 1 > r0l) s[nt][1] = -1e9f;
                if (c0 > r1l)     s[nt][2] = -1e9f;
                if (c0 + 1 > r1l) s[nt][3] = -1e9f;
            }
        }

        float mx0 = -1e30f, mx1 = -1e30f;
#pragma unroll
        for (int nt = 0; nt < 8; nt++) {
            mx0 = fmaxf(mx0, fmaxf(s[nt][0], s[nt][1]));
            mx1 = fmaxf(mx1, fmaxf(s[nt][2], s[nt][3]));
        }
        mx0 = fmaxf(mx0, __shfl_xor_sync(0xffffffffu, mx0, 1));
        mx0 = fmaxf(mx0, __shfl_xor_sync(0xffffffffu, mx0, 2));
        mx1 = fmaxf(mx1, __shfl_xor_sync(0xffffffffu, mx1, 1));
        mx1 = fmaxf(mx1, __shfl_xor_sync(0xffffffffu, mx1, 2));
        const float mn0 = fmaxf(m_[0], mx0), mn1 = fmaxf(m_[1], mx1);
        const float f0 = __expf(m_[0] - mn0), f1 = __expf(m_[1] - mn1);
        m_[0] = mn0; m_[1] = mn1;
        float rs0 = 0.f, rs1 = 0.f;
#pragma unroll
        for (int nt = 0; nt < 8; nt++) {
            s[nt][0] = __expf(s[nt][0] - mn0);
            s[nt][1] = __expf(s[nt][1] - mn0);
            s[nt][2] = __expf(s[nt][2] - mn1);
            s[nt][3] = __expf(s[nt][3] - mn1);
            rs0 += s[nt][0] + s[nt][1];
            rs1 += s[nt][2] + s[nt][3];
        }
        rs0 += __shfl_xor_sync(0xffffffffu, rs0, 1);
        rs0 += __shfl_xor_sync(0xffffffffu, rs0, 2);
        rs1 += __shfl_xor_sync(0xffffffffu, rs1, 1);
        rs1 += __shfl_xor_sync(0xffffffffu, rs1, 2);
        l_[0] = l_[0] * f0 + rs0;
        l_[1] = l_[1] * f1 + rs1;
#pragma unroll
        for (int nt = 0; nt < 8; nt++) {
            o[nt][0] *= f0; o[nt][1] *= f0; o[nt][2] *= f1; o[nt][3] *= f1;
        }

        uint32_t ph[4][4], pl[4][4];
#pragma unroll
        for (int kt = 0; kt < 4; kt++) {
            pack_split(s[2 * kt][0],     s[2 * kt][1],     ph[kt][0], pl[kt][0]);
            pack_split(s[2 * kt][2],     s[2 * kt][3],     ph[kt][1], pl[kt][1]);
            pack_split(s[2 * kt + 1][0], s[2 * kt + 1][1], ph[kt][2], pl[kt][2]);
            pack_split(s[2 * kt + 1][2], s[2 * kt + 1][3], ph[kt][3], pl[kt][3]);
        }

#pragma unroll
        for (int kt = 0; kt < 4; kt++) {
            const uint32_t vro = (uint32_t)((kt * 16 + vrow_l) * 144);
            uint32_t bh[8][2], bl[8][2];
#pragma unroll
            for (int g = 0; g < 4; g++) {
                uint32_t ro = vro + (uint32_t)((g * 16 + vcol_l) * 2);
                uint32_t r0, r1, r2, r3;
                LDSM_X4_T(r0, r1, r2, r3, vhb + ro);
                bh[2 * g + 0][0] = r0; bh[2 * g + 0][1] = r2;
                bh[2 * g + 1][0] = r1; bh[2 * g + 1][1] = r3;
                LDSM_X4_T(r0, r1, r2, r3, vlb + ro);
                bl[2 * g + 0][0] = r0; bl[2 * g + 0][1] = r2;
                bl[2 * g + 1][0] = r1; bl[2 * g + 1][1] = r3;
            }
#pragma unroll
            for (int nt = 0; nt < 8; nt++) {
                MMA_BF16(o[nt], ph[kt], bh[nt][0], bh[nt][1]);
                MMA_BF16(o[nt], ph[kt], bl[nt][0], bl[nt][1]);
                MMA_BF16(o[nt], pl[kt], bh[nt][0], bh[nt][1]);
            }
        }
    }

    const float inv0 = 1.f / l_[0], inv1 = 1.f / l_[1];
    const size_t row0 = rowbase + q0 + wid * 16 + (lane >> 2);
    const int col = colbase + (lane & 3) * 2;
    if (Of) {
#pragma unroll
        for (int nt = 0; nt < 8; nt++) {
            *(float2*)(Of + row0 * 1024 + col + nt * 8) =
                make_float2(o[nt][0] * inv0, o[nt][1] * inv0);
            *(float2*)(Of + (row0 + 8) * 1024 + col + nt * 8) =
                make_float2(o[nt][2] * inv1, o[nt][3] * inv1);
        }
    } else {
#pragma unroll
        for (int nt = 0; nt < 8; nt++) {
            uint32_t h01, l01, h23, l23;
            pack_split(o[nt][0] * inv0, o[nt][1] * inv0, h01, l01);
            pack_split(o[nt][2] * inv1, o[nt][3] * inv1, h23, l23);
            *(uint32_t*)(Oh + row0 * 1024 + col + nt * 8) = h01;
            *(uint32_t*)(Ol + row0 * 1024 + col + nt * 8) = l01;
            *(uint32_t*)(Oh + (row0 + 8) * 1024 + col + nt * 8) = h23;
            *(uint32_t*)(Ol + (row0 + 8) * 1024 + col + nt * 8) = l23;
        }
    }
}

// ================= launch =================
extern "C" void kernel_launch(void* const* d_in, const int* in_sizes, int n_in,
                              void* d_out, int out_size) {
    const float* x   = (const float*)d_in[0];
    const float* enc = (const float*)d_in[1];
    const float* w[6] = {(const float*)d_in[4], (const float*)d_in[5],
                         (const float*)d_in[6], (const float*)d_in[7],
                         (const float*)d_in[8], (const float*)d_in[9]};
    float* out = (float*)d_out;

    __nv_bfloat16 *qh, *ql, *kh, *kl, *vh, *vl, *ah, *al, *eh, *el, *wh, *wl;
    cudaGetSymbolAddress((void**)&qh, g_qh);
    cudaGetSymbolAddress((void**)&ql, g_ql);
    cudaGetSymbolAddress((void**)&kh, g_kh);
    cudaGetSymbolAddress((void**)&kl, g_kl);
    cudaGetSymbolAddress((void**)&vh, g_vh);
    cudaGetSymbolAddress((void**)&vl, g_vl);
    cudaGetSymbolAddress((void**)&ah, g_ah);
    cudaGetSymbolAddress((void**)&al, g_al);
    cudaGetSymbolAddress((void**)&eh, g_eh);
    cudaGetSymbolAddress((void**)&el, g_el);
    cudaGetSymbolAddress((void**)&wh, g_w6h);
    cudaGetSymbolAddress((void**)&wl, g_w6l);

    cudaFuncSetAttribute(gemm_qkv, cudaFuncAttributeMaxDynamicSharedMemorySize, GEMM_SMEM);
    cudaFuncSetAttribute(attn_mma, cudaFuncAttributeMaxDynamicSharedMemorySize, ATTN_SMEM);

    const size_t WSZ = (size_t)DMODEL * DMODEL;
    const int actBlocks = (MTOT * DMODEL) / (256 * 4);   // 4096
    const int wBlocks   = (int)(WSZ / (256 * 4));        // 1024
    dim3 gg(DMODEL / BN, MTOT / BM, 3);                  // (8, 32, 3)
    dim3 ga(SEQ / 64, NHEAD, BATCH);                     // (16, 16, 4)

    split_kernel<<<actBlocks, 256>>>(x, ah, al);
    split_kernel<<<actBlocks, 256>>>(enc, eh, el);
    for (int i = 0; i < 6; i++)
        split_kernel<<<wBlocks, 256>>>(w[i], wh + i * WSZ, wl + i * WSZ);

    // ---- self-attention block ----
    GemmTriple Ps;
    for (int zi = 0; zi < 3; zi++) {
        Ps.Ah[zi] = ah; Ps.Al[zi] = al;
        Ps.Bh[zi] = wh + zi * WSZ; Ps.Bl[zi] = wl + zi * WSZ;
    }
    Ps.Ch[0] = qh; Ps.Cl[0] = ql;
    Ps.Ch[1] = kh; Ps.Cl[1] = kl;
    Ps.Ch[2] = vh; Ps.Cl[2] = vl;
    gemm_qkv<<<gg, GT, GEMM_SMEM>>>(Ps);
    attn_mma<<<ga, 128, ATTN_SMEM>>>(qh, ql, kh, kl, vh, vl, nullptr, ah, al, 1);

    // ---- cross-attention block ----
    GemmTriple Pc;
    Pc.Ah[0] = ah; Pc.Al[0] = al;
    Pc.Ah[1] = eh; Pc.Al[1] = el;
    Pc.Ah[2] = eh; Pc.Al[2] = el;
    for (int zi = 0; zi < 3; zi++) {
        Pc.Bh[zi] = wh + (3 + zi) * WSZ; Pc.Bl[zi] = wl + (3 + zi) * WSZ;
    }
    Pc.Ch[0] = qh; Pc.Cl[0] = ql;
    Pc.Ch[1] = kh; Pc.Cl[1] = kl;
    Pc.Ch[2] = vh; Pc.Cl[2] = vl;
    gemm_qkv<<<gg, GT, GEMM_SMEM>>>(Pc);
    attn_mma<<<ga, 128, ATTN_SMEM>>>(qh, ql, kh, kl, vh, vl, out, nullptr, nullptr, 0);
}

// round 9
// speedup vs baseline: 1.2126x; 1.0847x over previous
#include <cuda_runtime.h>
#include <cuda_bf16.h>
#include <cstdint>

// DecoderBlock: self-MHA (causal) -> cross-MHA (no mask).
// B=4, S=1024, D=1024, H=16, DK=64.
// All matmuls mma.sync bf16 hi/lo split (fp32 accum).
// R9: GEMM 3-stage swizzled pipeline (96KB, 2 CTAs/SM), 1 barrier/k-tile.
//     Launch order puts gemm_qkv 6th (ncu -s 5 -c 1 captures it).

#define SEQ    1024
#define DMODEL 1024
#define NHEAD  16
#define HDIM   64
#define BATCH  4
#define MTOT   (BATCH * SEQ)   // 4096

// ---------------- scratch ----------------
__device__ __nv_bfloat16 g_qh[(size_t)MTOT * DMODEL];
__device__ __nv_bfloat16 g_ql[(size_t)MTOT * DMODEL];
__device__ __nv_bfloat16 g_kh[(size_t)MTOT * DMODEL];
__device__ __nv_bfloat16 g_kl[(size_t)MTOT * DMODEL];
__device__ __nv_bfloat16 g_vh[(size_t)MTOT * DMODEL];
__device__ __nv_bfloat16 g_vl[(size_t)MTOT * DMODEL];
__device__ __nv_bfloat16 g_ah[(size_t)MTOT * DMODEL];
__device__ __nv_bfloat16 g_al[(size_t)MTOT * DMODEL];
__device__ __nv_bfloat16 g_eh[(size_t)MTOT * DMODEL];
__device__ __nv_bfloat16 g_el[(size_t)MTOT * DMODEL];
__device__ __nv_bfloat16 g_w6h[6 * (size_t)DMODEL * DMODEL];
__device__ __nv_bfloat16 g_w6l[6 * (size_t)DMODEL * DMODEL];

// ================= PTX helpers =================
__device__ __forceinline__ uint32_t smem_u32(const void* p) {
    uint32_t a;
    asm("{ .reg .u64 t; cvta.to.shared.u64 t, %1; cvt.u32.u64 %0, t; }" : "=r"(a) : "l"(p));
    return a;
}
#define CP_ASYNC16(dst, src) asm volatile("cp.async.cg.shared.global [%0], [%1], 16;" :: "r"(dst), "l"(src))
#define CP_COMMIT()  asm volatile("cp.async.commit_group;" ::: "memory")
#define CP_WAIT1()   asm volatile("cp.async.wait_group 1;" ::: "memory")
#define CP_WAIT0()   asm volatile("cp.async.wait_group 0;" ::: "memory")

#define LDSM_X4(r0, r1, r2, r3, addr) \
    asm volatile("ldmatrix.sync.aligned.m8n8.x4.shared.b16 {%0,%1,%2,%3}, [%4];" \
                 : "=r"(r0), "=r"(r1), "=r"(r2), "=r"(r3) : "r"(addr))
#define LDSM_X4_T(r0, r1, r2, r3, addr) \
    asm volatile("ldmatrix.sync.aligned.m8n8.x4.trans.shared.b16 {%0,%1,%2,%3}, [%4];" \
                 : "=r"(r0), "=r"(r1), "=r"(r2), "=r"(r3) : "r"(addr))

#define MMA_BF16(c, a, b0v, b1v) \
    asm volatile("mma.sync.aligned.m16n8k16.row.col.f32.bf16.bf16.f32 " \
                 "{%0,%1,%2,%3}, {%4,%5,%6,%7}, {%8,%9}, {%0,%1,%2,%3};" \
                 : "+f"((c)[0]), "+f"((c)[1]), "+f"((c)[2]), "+f"((c)[3]) \
                 : "r"((a)[0]), "r"((a)[1]), "r"((a)[2]), "r"((a)[3]), \
                   "r"(b0v), "r"(b1v))

__device__ __forceinline__ void pack_split(float a, float b, uint32_t& h, uint32_t& l) {
    __nv_bfloat16 ha = __float2bfloat16(a), hb = __float2bfloat16(b);
    float ra = a - __bfloat162float(ha), rb = b - __bfloat162float(hb);
    __nv_bfloat162 hh = __halves2bfloat162(ha, hb);
    __nv_bfloat162 ll = __halves2bfloat162(__float2bfloat16(ra), __float2bfloat16(rb));
    h = *reinterpret_cast<uint32_t*>(&hh);
    l = *reinterpret_cast<uint32_t*>(&ll);
}

// ================= split fp32 -> bf16 hi/lo =================
__global__ __launch_bounds__(256) void split_kernel(const float* __restrict__ x,
                                                    __nv_bfloat16* __restrict__ hi,
                                                    __nv_bfloat16* __restrict__ lo) {
    size_t i = ((size_t)blockIdx.x * 256 + threadIdx.x) * 4;
    float4 v = *(const float4*)(x + i);
    uint32_t h0, l0, h1, l1;
    pack_split(v.x, v.y, h0, l0);
    pack_split(v.z, v.w, h1, l1);
    *(uint32_t*)(hi + i)     = h0; *(uint32_t*)(hi + i + 2) = h1;
    *(uint32_t*)(lo + i)     = l0; *(uint32_t*)(lo + i + 2) = l1;
}

// ================= fused-split mma.sync GEMM (QKV in one grid) =================
// C = A * B^T (4096x1024x1024) per z; 3 MMA passes: Ah*Bh + Ah*Bl + Al*Bh.
// CTA 128x128, 8 warps @64x32. 3-stage cp.async, XOR-swizzled 64B rows
// (chunk ^= (row>>1)&3), 96KB smem -> 2 CTAs/SM, ONE barrier per k-tile.
#define BM 128
#define BN 128
#define GT 256
#define TILE_B 8192                    // 128 rows * 64B
#define STAGE_B (4 * TILE_B)           // Ah, Al, Bh, Bl = 32768
#define NK 32
#define GEMM_SMEM (3 * STAGE_B)        // 98304

struct GemmTriple {
    const __nv_bfloat16* Ah[3];
    const __nv_bfloat16* Al[3];
    const __nv_bfloat16* Bh[3];
    const __nv_bfloat16* Bl[3];
    __nv_bfloat16* Ch[3];
    __nv_bfloat16* Cl[3];
};

__device__ __forceinline__ void issue_stage(uint32_t sbase,
                                            const __nv_bfloat16* Ahp, const __nv_bfloat16* Alp,
                                            const __nv_bfloat16* Bhp, const __nv_bfloat16* Blp,
                                            int kt, int tid) {
#pragma unroll
    for (int i = 0; i < 2; i++) {
        const int idx = tid + i * GT;                  // 0..511
        const int r = idx >> 2, c = idx & 3;
        const size_t goff = (size_t)r * 1024 + (size_t)kt * 32 + c * 8;
        const uint32_t soff = (uint32_t)(r * 64 + ((c ^ ((r >> 1) & 3)) * 16));
        CP_ASYNC16(sbase + 0 * TILE_B + soff, (const char*)(Ahp + goff));
        CP_ASYNC16(sbase + 1 * TILE_B + soff, (const char*)(Alp + goff));
        CP_ASYNC16(sbase + 2 * TILE_B + soff, (const char*)(Bhp + goff));
        CP_ASYNC16(sbase + 3 * TILE_B + soff, (const char*)(Blp + goff));
    }
}

__global__ __launch_bounds__(GT, 2)
void gemm_qkv(GemmTriple P) {
    extern __shared__ char smc[];
    uint32_t sb = smem_u32(smc);
    const int tid = threadIdx.x;
    const int wid = tid >> 5, lane = tid & 31;
    const int z = blockIdx.z;
    const int m0 = blockIdx.y * BM;
    const int n0 = blockIdx.x * BN;
    const int wm = (wid & 1) * 64;
    const int wn = (wid >> 1) * 32;

    const __nv_bfloat16* Ahp = P.Ah[z] + (size_t)m0 * 1024;
    const __nv_bfloat16* Alp = P.Al[z] + (size_t)m0 * 1024;
    const __nv_bfloat16* Bhp = P.Bh[z] + (size_t)n0 * 1024;
    const __nv_bfloat16* Blp = P.Bl[z] + (size_t)n0 * 1024;

    const int lrow = (lane & 7) + ((lane >> 3) & 1) * 8;
    const int hi5 = (lane >> 4) & 1;   // k-half chunk bit

    float acc[4][4][4];
#pragma unroll
    for (int mt = 0; mt < 4; mt++)
#pragma unroll
        for (int nt = 0; nt < 4; nt++)
#pragma unroll
            for (int q = 0; q < 4; q++) acc[mt][nt][q] = 0.f;

    // per-lane swizzled row offsets (row*64 fixed per mt/g; chunk xor varies by ks)
    issue_stage(sb + 0 * STAGE_B, Ahp, Alp, Bhp, Blp, 0, tid);
    CP_COMMIT();
    issue_stage(sb + 1 * STAGE_B, Ahp, Alp, Bhp, Blp, 1, tid);
    CP_COMMIT();

    for (int kt = 0; kt < NK; kt++) {
        CP_WAIT1();            // stage kt landed ({kt, kt+1} were pending)
        __syncthreads();       // also guarantees buffer (kt+2)%3 fully consumed (computed in kt-1)
        if (kt + 2 < NK)
            issue_stage(sb + ((kt + 2) % 3) * STAGE_B, Ahp, Alp, Bhp, Blp, kt + 2, tid);
        CP_COMMIT();

        const uint32_t stb = sb + (kt % 3) * STAGE_B;
#pragma unroll
        for (int ks = 0; ks < 2; ks++) {
            uint32_t ah[4][4], al[4][4];
#pragma unroll
            for (int mt = 0; mt < 4; mt++) {
                const int row = wm + mt * 16 + lrow;
                const uint32_t ro = (uint32_t)(row * 64 +
                    (((ks * 2 + hi5) ^ ((row >> 1) & 3)) * 16));
                LDSM_X4(ah[mt][0], ah[mt][1], ah[mt][2], ah[mt][3], stb + ro);
                LDSM_X4(al[mt][0], al[mt][1], al[mt][2], al[mt][3], stb + TILE_B + ro);
            }
#pragma unroll
            for (int g = 0; g < 2; g++) {   // two 16-col B groups -> nt = 2g, 2g+1
                const int row = wn + g * 16 + lrow;
                const uint32_t ro = (uint32_t)(row * 64 +
                    (((ks * 2 + hi5) ^ ((row >> 1) & 3)) * 16));
                uint32_t h0, h1, h2, h3, l0, l1, l2, l3;
                LDSM_X4(h0, h1, h2, h3, stb + 2 * TILE_B + ro);
                LDSM_X4(l0, l1, l2, l3, stb + 3 * TILE_B + ro);
#pragma unroll
                for (int mt = 0; mt < 4; mt++) {
                    MMA_BF16(acc[mt][2 * g + 0], ah[mt], h0, h2);
                    MMA_BF16(acc[mt][2 * g + 0], ah[mt], l0, l2);
                    MMA_BF16(acc[mt][2 * g + 0], al[mt], h0, h2);
                    MMA_BF16(acc[mt][2 * g + 1], ah[mt], h1, h3);
                    MMA_BF16(acc[mt][2 * g + 1], ah[mt], l1, l3);
                    MMA_BF16(acc[mt][2 * g + 1], al[mt], h1, h3);
                }
            }
        }
    }

    __nv_bfloat16* Ch = P.Ch[z];
    __nv_bfloat16* Cl = P.Cl[z];
#pragma unroll
    for (int mt = 0; mt < 4; mt++) {
#pragma unroll
        for (int nt = 0; nt < 4; nt++) {
            int row = m0 + wm + mt * 16 + (lane >> 2);
            int col = n0 + wn + nt * 8 + (lane & 3) * 2;
            uint32_t h01, l01, h23, l23;
            pack_split(acc[mt][nt][0], acc[mt][nt][1], h01, l01);
            pack_split(acc[mt][nt][2], acc[mt][nt][3], h23, l23);
            *(uint32_t*)(Ch + (size_t)row * 1024 + col) = h01;
            *(uint32_t*)(Cl + (size_t)row * 1024 + col) = l01;
            *(uint32_t*)(Ch + (size_t)(row + 8) * 1024 + col) = h23;
            *(uint32_t*)(Cl + (size_t)(row + 8) * 1024 + col) = l23;
        }
    }
}

// ================= tensor-core flash attention (bf16 split, fp32 softmax) =================
#define APITCH 72
#define ATILE_B2 (64 * APITCH * 2)    // 9216
#define AQ_H 0
#define AQ_L ATILE_B2
#define AST(s, t) (2 * ATILE_B2 + (s) * (4 * ATILE_B2) + (t) * ATILE_B2)
#define ATTN_SMEM (2 * ATILE_B2 + 2 * 4 * ATILE_B2)   // 92160

__device__ __forceinline__ void attn_load_tile(uint32_t dst, const __nv_bfloat16* src, int tid) {
#pragma unroll
    for (int i = 0; i < 4; i++) {
        int idx = tid + i * 128;
        int r = idx >> 3, c = idx & 7;
        CP_ASYNC16(dst + (uint32_t)(r * 144 + c * 16),
                   (const char*)(src + (size_t)r * 1024 + c * 8));
    }
}

__global__ __launch_bounds__(128, 2)
void attn_mma(const __nv_bfloat16* __restrict__ Qh, const __nv_bfloat16* __restrict__ Ql,
              const __nv_bfloat16* __restrict__ Kh, const __nv_bfloat16* __restrict__ Kl,
              const __nv_bfloat16* __restrict__ Vh, const __nv_bfloat16* __restrict__ Vl,
              float* __restrict__ Of,
              __nv_bfloat16* __restrict__ Oh, __nv_bfloat16* __restrict__ Ol,
              int causal) {
    extern __shared__ char smc[];
    uint32_t sb = smem_u32(smc);
    const int tid = threadIdx.x;
    const int wid = tid >> 5, lane = tid & 31;
    const int q0 = blockIdx.x * 64;
    const int h = blockIdx.y, b = blockIdx.z;
    const size_t rowbase = (size_t)(b * SEQ);
    const int colbase = h * HDIM;

    const int lrow = (lane & 7) + ((lane >> 3) & 1) * 8;
    const int lkof = ((lane >> 4) & 1) * 8;
    const int vrow_l = (lane & 7) + ((lane >> 4) & 1) * 8;
    const int vcol_l = ((lane >> 3) & 1) * 8;

    attn_load_tile(sb + AQ_H, Qh + (rowbase + q0) * 1024 + colbase, tid);
    attn_load_tile(sb + AQ_L, Ql + (rowbase + q0) * 1024 + colbase, tid);
    attn_load_tile(sb + AST(0, 0), Kh + rowbase * 1024 + colbase, tid);
    attn_load_tile(sb + AST(0, 1), Kl + rowbase * 1024 + colbase, tid);
    attn_load_tile(sb + AST(0, 2), Vh + rowbase * 1024 + colbase, tid);
    attn_load_tile(sb + AST(0, 3), Vl + rowbase * 1024 + colbase, tid);
    CP_COMMIT();

    const int njt = causal ? (blockIdx.x + 1) : (SEQ / 64);

    uint32_t qhf[4][4], qlf[4][4];
    float o[8][4];
#pragma unroll
    for (int nt = 0; nt < 8; nt++)
#pragma unroll
        for (int q = 0; q < 4; q++) o[nt][q] = 0.f;
    float m_[2] = {-1e30f, -1e30f}, l_[2] = {0.f, 0.f};

    for (int j = 0; j < njt; j++) {
        CP_WAIT0();
        __syncthreads();
        if (j + 1 < njt) {
            const size_t kb = (rowbase + (size_t)(j + 1) * 64) * 1024 + colbase;
            const int s = (j + 1) & 1;
            attn_load_tile(sb + AST(s, 0), Kh + kb, tid);
            attn_load_tile(sb + AST(s, 1), Kl + kb, tid);
            attn_load_tile(sb + AST(s, 2), Vh + kb, tid);
            attn_load_tile(sb + AST(s, 3), Vl + kb, tid);
            CP_COMMIT();
        }
        if (j == 0) {
#pragma unroll
            for (int kt = 0; kt < 4; kt++) {
                uint32_t ro = (uint32_t)((wid * 16 + lrow) * 144 + (kt * 16 + lkof) * 2);
                LDSM_X4(qhf[kt][0], qhf[kt][1], qhf[kt][2], qhf[kt][3], sb + AQ_H + ro);
                LDSM_X4(qlf[kt][0], qlf[kt][1], qlf[kt][2], qlf[kt][3], sb + AQ_L + ro);
            }
        }

        const uint32_t khb = sb + AST(j & 1, 0);
        const uint32_t klb = sb + AST(j & 1, 1);
        const uint32_t vhb = sb + AST(j & 1, 2);
        const uint32_t vlb = sb + AST(j & 1, 3);

        float s[8][4];
#pragma unroll
        for (int nt = 0; nt < 8; nt++)
#pragma unroll
            for (int q = 0; q < 4; q++) s[nt][q] = 0.f;
#pragma unroll
        for (int kt = 0; kt < 4; kt++) {
            uint32_t bh[8][2], bl[8][2];
#pragma unroll
            for (int g = 0; g < 4; g++) {
                uint32_t ro = (uint32_t)((g * 16 + lrow) * 144 + (kt * 16 + lkof) * 2);
                uint32_t r0, r1, r2, r3;
                LDSM_X4(r0, r1, r2, r3, khb + ro);
                bh[2 * g + 0][0] = r0; bh[2 * g + 0][1] = r2;
                bh[2 * g + 1][0] = r1; bh[2 * g + 1][1] = r3;
                LDSM_X4(r0, r1, r2, r3, klb + ro);
                bl[2 * g + 0][0] = r0; bl[2 * g + 0][1] = r2;
                bl[2 * g + 1][0] = r1; bl[2 * g + 1][1] = r3;
            }
#pragma unroll
            for (int nt = 0; nt < 8; nt++) {
                MMA_BF16(s[nt], qhf[kt], bh[nt][0], bh[nt][1]);
                MMA_BF16(s[nt], qhf[kt], bl[nt][0], bl[nt][1]);
                MMA_BF16(s[nt], qlf[kt], bh[nt][0], bh[nt][1]);
            }
        }

#pragma unroll
        for (int nt = 0; nt < 8; nt++)
#pragma unroll
            for (int q = 0; q < 4; q++) s[nt][q] *= 0.125f;
        if (causal && j == njt - 1) {
            const int r0l = wid * 16 + (lane >> 2), r1l = r0l + 8;
#pragma unroll
            for (int nt = 0; nt < 8; nt++) {
                const int c0 = nt * 8 + (lane & 3) * 2;
                if (c0 > r0l)     s[nt][0] = -1e9f;
                if (c0 + 1 > r0l) s[nt][1] = -1e9f;
                if (c0 > r1l)     s[nt][2] = -1e9f;
                if (c0 + 1 > r1l) s[nt][3] = -1e9f;
            }
        }

        float mx0 = -1e30f, mx1 = -1e30f;
#pragma unroll
        for (int nt = 0; nt < 8; nt++) {
            mx0 = fmaxf(mx0, fmaxf(s[nt][0], s[nt][1]));
            mx1 = fmaxf(mx1, fmaxf(s[nt][2], s[nt][3]));
        }
        mx0 = fmaxf(mx0, __shfl_xor_sync(0xffffffffu, mx0, 1));
        mx0 = fmaxf(mx0, __shfl_xor_sync(0xffffffffu, mx0, 2));
        mx1 = fmaxf(mx1, __shfl_xor_sync(0xffffffffu, mx1, 1));
        mx1 = fmaxf(mx1, __shfl_xor_sync(0xffffffffu, mx1, 2));
        const float mn0 = fmaxf(m_[0], mx0), mn1 = fmaxf(m_[1], mx1);
        const float f0 = __expf(m_[0] - mn0), f1 = __expf(m_[1] - mn1);
        m_[0] = mn0; m_[1] = mn1;
        float rs0 = 0.f, rs1 = 0.f;
#pragma unroll
        for (int nt = 0; nt < 8; nt++) {
            s[nt][0] = __expf(s[nt][0] - mn0);
            s[nt][1] = __expf(s[nt][1] - mn0);
            s[nt][2] = __expf(s[nt][2] - mn1);
            s[nt][3] = __expf(s[nt][3] - mn1);
            rs0 += s[nt][0] + s[nt][1];
            rs1 += s[nt][2] + s[nt][3];
        }
        rs0 += __shfl_xor_sync(0xffffffffu, rs0, 1);
        rs0 += __shfl_xor_sync(0xffffffffu, rs0, 2);
        rs1 += __shfl_xor_sync(0xffffffffu, rs1, 1);
        rs1 += __shfl_xor_sync(0xffffffffu, rs1, 2);
        l_[0] = l_[0] * f0 + rs0;
        l_[1] = l_[1] * f1 + rs1;
#pragma unroll
        for (int nt = 0; nt < 8; nt++) {
            o[nt][0] *= f0; o[nt][1] *= f0; o[nt][2] *= f1; o[nt][3] *= f1;
        }

        uint32_t ph[4][4], pl[4][4];
#pragma unroll
        for (int kt = 0; kt < 4; kt++) {
            pack_split(s[2 * kt][0],     s[2 * kt][1],     ph[kt][0], pl[kt][0]);
            pack_split(s[2 * kt][2],     s[2 * kt][3],     ph[kt][1], pl[kt][1]);
            pack_split(s[2 * kt + 1][0], s[2 * kt + 1][1], ph[kt][2], pl[kt][2]);
            pack_split(s[2 * kt + 1][2], s[2 * kt + 1][3], ph[kt][3], pl[kt][3]);
        }

#pragma unroll
        for (int kt = 0; kt < 4; kt++) {
            const uint32_t vro = (uint32_t)((kt * 16 + vrow_l) * 144);
            uint32_t bh[8][2], bl[8][2];
#pragma unroll
            for (int g = 0; g < 4; g++) {
                uint32_t ro = vro + (uint32_t)((g * 16 + vcol_l) * 2);
                uint32_t r0, r1, r2, r3;
                LDSM_X4_T(r0, r1, r2, r3, vhb + ro);
                bh[2 * g + 0][0] = r0; bh[2 * g + 0][1] = r2;
                bh[2 * g + 1][0] = r1; bh[2 * g + 1][1] = r3;
                LDSM_X4_T(r0, r1, r2, r3, vlb + ro);
                bl[2 * g + 0][0] = r0; bl[2 * g + 0][1] = r2;
                bl[2 * g + 1][0] = r1; bl[2 * g + 1][1] = r3;
            }
#pragma unroll
            for (int nt = 0; nt < 8; nt++) {
                MMA_BF16(o[nt], ph[kt], bh[nt][0], bh[nt][1]);
                MMA_BF16(o[nt], ph[kt], bl[nt][0], bl[nt][1]);
                MMA_BF16(o[nt], pl[kt], bh[nt][0], bh[nt][1]);
            }
        }
    }

    const float inv0 = 1.f / l_[0], inv1 = 1.f / l_[1];
    const size_t row0 = rowbase + q0 + wid * 16 + (lane >> 2);
    const int col = colbase + (lane & 3) * 2;
    if (Of) {
#pragma unroll
        for (int nt = 0; nt < 8; nt++) {
            *(float2*)(Of + row0 * 1024 + col + nt * 8) =
                make_float2(o[nt][0] * inv0, o[nt][1] * inv0);
            *(float2*)(Of + (row0 + 8) * 1024 + col + nt * 8) =
                make_float2(o[nt][2] * inv1, o[nt][3] * inv1);
        }
    } else {
#pragma unroll
        for (int nt = 0; nt < 8; nt++) {
            uint32_t h01, l01, h23, l23;
            pack_split(o[nt][0] * inv0, o[nt][1] * inv0, h01, l01);
            pack_split(o[nt][2] * inv1, o[nt][3] * inv1, h23, l23);
            *(uint32_t*)(Oh + row0 * 1024 + col + nt * 8) = h01;
            *(uint32_t*)(Ol + row0 * 1024 + col + nt * 8) = l01;
            *(uint32_t*)(Oh + (row0 + 8) * 1024 + col + nt * 8) = h23;
            *(uint32_t*)(Ol + (row0 + 8) * 1024 + col + nt * 8) = l23;
        }
    }
}

// ================= launch =================
extern "C" void kernel_launch(void* const* d_in, const int* in_sizes, int n_in,
                              void* d_out, int out_size) {
    const float* x   = (const float*)d_in[0];
    const float* enc = (const float*)d_in[1];
    const float* w[6] = {(const float*)d_in[4], (const float*)d_in[5],
                         (const float*)d_in[6], (const float*)d_in[7],
                         (const float*)d_in[8], (const float*)d_in[9]};
    float* out = (float*)d_out;

    __nv_bfloat16 *qh, *ql, *kh, *kl, *vh, *vl, *ah, *al, *eh, *el, *wh, *wl;
    cudaGetSymbolAddress((void**)&qh, g_qh);
    cudaGetSymbolAddress((void**)&ql, g_ql);
    cudaGetSymbolAddress((void**)&kh, g_kh);
    cudaGetSymbolAddress((void**)&kl, g_kl);
    cudaGetSymbolAddress((void**)&vh, g_vh);
    cudaGetSymbolAddress((void**)&vl, g_vl);
    cudaGetSymbolAddress((void**)&ah, g_ah);
    cudaGetSymbolAddress((void**)&al, g_al);
    cudaGetSymbolAddress((void**)&eh, g_eh);
    cudaGetSymbolAddress((void**)&el, g_el);
    cudaGetSymbolAddress((void**)&wh, g_w6h);
    cudaGetSymbolAddress((void**)&wl, g_w6l);

    cudaFuncSetAttribute(gemm_qkv, cudaFuncAttributeMaxDynamicSharedMemorySize, GEMM_SMEM);
    cudaFuncSetAttribute(attn_mma, cudaFuncAttributeMaxDynamicSharedMemorySize, ATTN_SMEM);

    const size_t WSZ = (size_t)DMODEL * DMODEL;
    const int actBlocks = (MTOT * DMODEL) / (256 * 4);   // 4096
    const int wBlocks   = (int)(WSZ / (256 * 4));        // 1024
    dim3 gg(DMODEL / BN, MTOT / BM, 3);                  // (8, 32, 3)
    dim3 ga(SEQ / 64, NHEAD, BATCH);                     // (16, 16, 4)

    // launches 1..5: exactly the splits gemm_s needs (+enc) so launch #6 = gemm_qkv
    split_kernel<<<actBlocks, 256>>>(x, ah, al);                       // 1
    split_kernel<<<wBlocks, 256>>>(w[0], wh + 0 * WSZ, wl + 0 * WSZ);  // 2
    split_kernel<<<wBlocks, 256>>>(w[1], wh + 1 * WSZ, wl + 1 * WSZ);  // 3
    split_kernel<<<wBlocks, 256>>>(w[2], wh + 2 * WSZ, wl + 2 * WSZ);  // 4
    split_kernel<<<actBlocks, 256>>>(enc, eh, el);                     // 5

    // ---- self-attention block ----
    GemmTriple Ps;
    for (int zi = 0; zi < 3; zi++) {
        Ps.Ah[zi] = ah; Ps.Al[zi] = al;
        Ps.Bh[zi] = wh + zi * WSZ; Ps.Bl[zi] = wl + zi * WSZ;
    }
    Ps.Ch[0] = qh; Ps.Cl[0] = ql;
    Ps.Ch[1] = kh; Ps.Cl[1] = kl;
    Ps.Ch[2] = vh; Ps.Cl[2] = vl;
    gemm_qkv<<<gg, GT, GEMM_SMEM>>>(Ps);                               // 6 (profiled)
    attn_mma<<<ga, 128, ATTN_SMEM>>>(qh, ql, kh, kl, vh, vl, nullptr, ah, al, 1);  // 7

    // ---- cross-attention block ----
    split_kernel<<<wBlocks, 256>>>(w[3], wh + 3 * WSZ, wl + 3 * WSZ);  // 8
    split_kernel<<<wBlocks, 256>>>(w[4], wh + 4 * WSZ, wl + 4 * WSZ);  // 9
    split_kernel<<<wBlocks, 256>>>(w[5], wh + 5 * WSZ, wl + 5 * WSZ);  // 10
    GemmTriple Pc;
    Pc.Ah[0] = ah; Pc.Al[0] = al;
    Pc.Ah[1] = eh; Pc.Al[1] = el;
    Pc.Ah[2] = eh; Pc.Al[2] = el;
    for (int zi = 0; zi < 3; zi++) {
        Pc.Bh[zi] = wh + (3 + zi) * WSZ; Pc.Bl[zi] = wl + (3 + zi) * WSZ;
    }
    Pc.Ch[0] = qh; Pc.Cl[0] = ql;
    Pc.Ch[1] = kh; Pc.Cl[1] = kl;
    Pc.Ch[2] = vh; Pc.Cl[2] = vl;
    gemm_qkv<<<gg, GT, GEMM_SMEM>>>(Pc);                               // 11
    attn_mma<<<ga, 128, ATTN_SMEM>>>(qh, ql, kh, kl, vh, vl, out, nullptr, nullptr, 0);  // 12
}

// round 10
// speedup vs baseline: 1.2412x; 1.0235x over previous
#include <cuda_runtime.h>
#include <cuda_bf16.h>
#include <cstdint>

// DecoderBlock: self-MHA (causal) -> cross-MHA (no mask).
// B=4, S=1024, D=1024, H=16, DK=64.
// All matmuls mma.sync bf16 hi/lo split (fp32 accum).
// R10: pass-outer MMA ordering (8 independent MMAs between acc reuse) in GEMM+attn;
//      split kernels batched into 2 launches.

#define SEQ    1024
#define DMODEL 1024
#define NHEAD  16
#define HDIM   64
#define BATCH  4
#define MTOT   (BATCH * SEQ)   // 4096

// ---------------- scratch ----------------
__device__ __nv_bfloat16 g_qh[(size_t)MTOT * DMODEL];
__device__ __nv_bfloat16 g_ql[(size_t)MTOT * DMODEL];
__device__ __nv_bfloat16 g_kh[(size_t)MTOT * DMODEL];
__device__ __nv_bfloat16 g_kl[(size_t)MTOT * DMODEL];
__device__ __nv_bfloat16 g_vh[(size_t)MTOT * DMODEL];
__device__ __nv_bfloat16 g_vl[(size_t)MTOT * DMODEL];
__device__ __nv_bfloat16 g_ah[(size_t)MTOT * DMODEL];
__device__ __nv_bfloat16 g_al[(size_t)MTOT * DMODEL];
__device__ __nv_bfloat16 g_eh[(size_t)MTOT * DMODEL];
__device__ __nv_bfloat16 g_el[(size_t)MTOT * DMODEL];
__device__ __nv_bfloat16 g_w6h[6 * (size_t)DMODEL * DMODEL];
__device__ __nv_bfloat16 g_w6l[6 * (size_t)DMODEL * DMODEL];

// ================= PTX helpers =================
__device__ __forceinline__ uint32_t smem_u32(const void* p) {
    uint32_t a;
    asm("{ .reg .u64 t; cvta.to.shared.u64 t, %1; cvt.u32.u64 %0, t; }" : "=r"(a) : "l"(p));
    return a;
}
#define CP_ASYNC16(dst, src) asm volatile("cp.async.cg.shared.global [%0], [%1], 16;" :: "r"(dst), "l"(src))
#define CP_COMMIT()  asm volatile("cp.async.commit_group;" ::: "memory")
#define CP_WAIT1()   asm volatile("cp.async.wait_group 1;" ::: "memory")
#define CP_WAIT0()   asm volatile("cp.async.wait_group 0;" ::: "memory")

#define LDSM_X4(r0, r1, r2, r3, addr) \
    asm volatile("ldmatrix.sync.aligned.m8n8.x4.shared.b16 {%0,%1,%2,%3}, [%4];" \
                 : "=r"(r0), "=r"(r1), "=r"(r2), "=r"(r3) : "r"(addr))
#define LDSM_X4_T(r0, r1, r2, r3, addr) \
    asm volatile("ldmatrix.sync.aligned.m8n8.x4.trans.shared.b16 {%0,%1,%2,%3}, [%4];" \
                 : "=r"(r0), "=r"(r1), "=r"(r2), "=r"(r3) : "r"(addr))

#define MMA_BF16(c, a, b0v, b1v) \
    asm volatile("mma.sync.aligned.m16n8k16.row.col.f32.bf16.bf16.f32 " \
                 "{%0,%1,%2,%3}, {%4,%5,%6,%7}, {%8,%9}, {%0,%1,%2,%3};" \
                 : "+f"((c)[0]), "+f"((c)[1]), "+f"((c)[2]), "+f"((c)[3]) \
                 : "r"((a)[0]), "r"((a)[1]), "r"((a)[2]), "r"((a)[3]), \
                   "r"(b0v), "r"(b1v))

__device__ __forceinline__ void pack_split(float a, float b, uint32_t& h, uint32_t& l) {
    __nv_bfloat16 ha = __float2bfloat16(a), hb = __float2bfloat16(b);
    float ra = a - __bfloat162float(ha), rb = b - __bfloat162float(hb);
    __nv_bfloat162 hh = __halves2bfloat162(ha, hb);
    __nv_bfloat162 ll = __halves2bfloat162(__float2bfloat16(ra), __float2bfloat16(rb));
    h = *reinterpret_cast<uint32_t*>(&hh);
    l = *reinterpret_cast<uint32_t*>(&ll);
}

// ================= batched split fp32 -> bf16 hi/lo =================
struct SplitBatch {
    const float* src[6];
    __nv_bfloat16* hi[6];
    __nv_bfloat16* lo[6];
};

__global__ __launch_bounds__(256) void split_multi(SplitBatch S) {
    const float* x = S.src[blockIdx.y];
    __nv_bfloat16* hi = S.hi[blockIdx.y];
    __nv_bfloat16* lo = S.lo[blockIdx.y];
    size_t i = ((size_t)blockIdx.x * 256 + threadIdx.x) * 4;
    float4 v = *(const float4*)(x + i);
    uint32_t h0, l0, h1, l1;
    pack_split(v.x, v.y, h0, l0);
    pack_split(v.z, v.w, h1, l1);
    *(uint32_t*)(hi + i)     = h0; *(uint32_t*)(hi + i + 2) = h1;
    *(uint32_t*)(lo + i)     = l0; *(uint32_t*)(lo + i + 2) = l1;
}

// ================= fused-split mma.sync GEMM (QKV in one grid) =================
// C = A * B^T (4096x1024x1024) per z; 3 passes ordered pass-outer (indep MMAs).
// CTA 128x128, 8 warps @64x32. 3-stage cp.async, XOR-swizzled 64B rows,
// 96KB smem -> 2 CTAs/SM, one barrier per k-tile.
#define BM 128
#define BN 128
#define GT 256
#define TILE_B 8192                    // 128 rows * 64B
#define STAGE_B (4 * TILE_B)           // Ah, Al, Bh, Bl = 32768
#define NK 32
#define GEMM_SMEM (3 * STAGE_B)        // 98304

struct GemmTriple {
    const __nv_bfloat16* Ah[3];
    const __nv_bfloat16* Al[3];
    const __nv_bfloat16* Bh[3];
    const __nv_bfloat16* Bl[3];
    __nv_bfloat16* Ch[3];
    __nv_bfloat16* Cl[3];
};

__device__ __forceinline__ void issue_stage(uint32_t sbase,
                                            const __nv_bfloat16* Ahp, const __nv_bfloat16* Alp,
                                            const __nv_bfloat16* Bhp, const __nv_bfloat16* Blp,
                                            int kt, int tid) {
#pragma unroll
    for (int i = 0; i < 2; i++) {
        const int idx = tid + i * GT;                  // 0..511
        const int r = idx >> 2, c = idx & 3;
        const size_t goff = (size_t)r * 1024 + (size_t)kt * 32 + c * 8;
        const uint32_t soff = (uint32_t)(r * 64 + ((c ^ ((r >> 1) & 3)) * 16));
        CP_ASYNC16(sbase + 0 * TILE_B + soff, (const char*)(Ahp + goff));
        CP_ASYNC16(sbase + 1 * TILE_B + soff, (const char*)(Alp + goff));
        CP_ASYNC16(sbase + 2 * TILE_B + soff, (const char*)(Bhp + goff));
        CP_ASYNC16(sbase + 3 * TILE_B + soff, (const char*)(Blp + goff));
    }
}

__global__ __launch_bounds__(GT, 2)
void gemm_qkv(GemmTriple P) {
    extern __shared__ char smc[];
    uint32_t sb = smem_u32(smc);
    const int tid = threadIdx.x;
    const int wid = tid >> 5, lane = tid & 31;
    const int z = blockIdx.z;
    const int m0 = blockIdx.y * BM;
    const int n0 = blockIdx.x * BN;
    const int wm = (wid & 1) * 64;
    const int wn = (wid >> 1) * 32;

    const __nv_bfloat16* Ahp = P.Ah[z] + (size_t)m0 * 1024;
    const __nv_bfloat16* Alp = P.Al[z] + (size_t)m0 * 1024;
    const __nv_bfloat16* Bhp = P.Bh[z] + (size_t)n0 * 1024;
    const __nv_bfloat16* Blp = P.Bl[z] + (size_t)n0 * 1024;

    const int lrow = (lane & 7) + ((lane >> 3) & 1) * 8;
    const int hi5 = (lane >> 4) & 1;   // k-half chunk bit

    float acc[4][4][4];
#pragma unroll
    for (int mt = 0; mt < 4; mt++)
#pragma unroll
        for (int nt = 0; nt < 4; nt++)
#pragma unroll
            for (int q = 0; q < 4; q++) acc[mt][nt][q] = 0.f;

    issue_stage(sb + 0 * STAGE_B, Ahp, Alp, Bhp, Blp, 0, tid);
    CP_COMMIT();
    issue_stage(sb + 1 * STAGE_B, Ahp, Alp, Bhp, Blp, 1, tid);
    CP_COMMIT();

    for (int kt = 0; kt < NK; kt++) {
        CP_WAIT1();            // stage kt landed
        __syncthreads();       // buffer (kt+2)%3 fully consumed (computed in kt-1)
        if (kt + 2 < NK)
            issue_stage(sb + ((kt + 2) % 3) * STAGE_B, Ahp, Alp, Bhp, Blp, kt + 2, tid);
        CP_COMMIT();

        const uint32_t stb = sb + (kt % 3) * STAGE_B;
#pragma unroll
        for (int ks = 0; ks < 2; ks++) {
            uint32_t ah[4][4], al[4][4];
#pragma unroll
            for (int mt = 0; mt < 4; mt++) {
                const int row = wm + mt * 16 + lrow;
                const uint32_t ro = (uint32_t)(row * 64 +
                    (((ks * 2 + hi5) ^ ((row >> 1) & 3)) * 16));
                LDSM_X4(ah[mt][0], ah[mt][1], ah[mt][2], ah[mt][3], stb + ro);
                LDSM_X4(al[mt][0], al[mt][1], al[mt][2], al[mt][3], stb + TILE_B + ro);
            }
#pragma unroll
            for (int g = 0; g < 2; g++) {   // two 16-col B groups -> nt = 2g, 2g+1
                const int row = wn + g * 16 + lrow;
                const uint32_t ro = (uint32_t)(row * 64 +
                    (((ks * 2 + hi5) ^ ((row >> 1) & 3)) * 16));
                uint32_t h0, h1, h2, h3, l0, l1, l2, l3;
                LDSM_X4(h0, h1, h2, h3, stb + 2 * TILE_B + ro);
                LDSM_X4(l0, l1, l2, l3, stb + 3 * TILE_B + ro);
                // pass 1: Ah * Bh  (8 independent MMAs)
#pragma unroll
                for (int mt = 0; mt < 4; mt++) {
                    MMA_BF16(acc[mt][2 * g + 0], ah[mt], h0, h2);
                    MMA_BF16(acc[mt][2 * g + 1], ah[mt], h1, h3);
                }
                // pass 2: Ah * Bl
#pragma unroll
                for (int mt = 0; mt < 4; mt++) {
                    MMA_BF16(acc[mt][2 * g + 0], ah[mt], l0, l2);
                    MMA_BF16(acc[mt][2 * g + 1], ah[mt], l1, l3);
                }
                // pass 3: Al * Bh
#pragma unroll
                for (int mt = 0; mt < 4; mt++) {
                    MMA_BF16(acc[mt][2 * g + 0], al[mt], h0, h2);
                    MMA_BF16(acc[mt][2 * g + 1], al[mt], h1, h3);
                }
            }
        }
    }

    __nv_bfloat16* Ch = P.Ch[z];
    __nv_bfloat16* Cl = P.Cl[z];
#pragma unroll
    for (int mt = 0; mt < 4; mt++) {
#pragma unroll
        for (int nt = 0; nt < 4; nt++) {
            int row = m0 + wm + mt * 16 + (lane >> 2);
            int col = n0 + wn + nt * 8 + (lane & 3) * 2;
            uint32_t h01, l01, h23, l23;
            pack_split(acc[mt][nt][0], acc[mt][nt][1], h01, l01);
            pack_split(acc[mt][nt][2], acc[mt][nt][3], h23, l23);
            *(uint32_t*)(Ch + (size_t)row * 1024 + col) = h01;
            *(uint32_t*)(Cl + (size_t)row * 1024 + col) = l01;
            *(uint32_t*)(Ch + (size_t)(row + 8) * 1024 + col) = h23;
            *(uint32_t*)(Cl + (size_t)(row + 8) * 1024 + col) = l23;
        }
    }
}

// ================= tensor-core flash attention (bf16 split, fp32 softmax) =================
#define APITCH 72
#define ATILE_B2 (64 * APITCH * 2)    // 9216
#define AQ_H 0
#define AQ_L ATILE_B2
#define AST(s, t) (2 * ATILE_B2 + (s) * (4 * ATILE_B2) + (t) * ATILE_B2)
#define ATTN_SMEM (2 * ATILE_B2 + 2 * 4 * ATILE_B2)   // 92160

__device__ __forceinline__ void attn_load_tile(uint32_t dst, const __nv_bfloat16* src, int tid) {
#pragma unroll
    for (int i = 0; i < 4; i++) {
        int idx = tid + i * 128;
        int r = idx >> 3, c = idx & 7;
        CP_ASYNC16(dst + (uint32_t)(r * 144 + c * 16),
                   (const char*)(src + (size_t)r * 1024 + c * 8));
    }
}

__global__ __launch_bounds__(128, 2)
void attn_mma(const __nv_bfloat16* __restrict__ Qh, const __nv_bfloat16* __restrict__ Ql,
              const __nv_bfloat16* __restrict__ Kh, const __nv_bfloat16* __restrict__ Kl,
              const __nv_bfloat16* __restrict__ Vh, const __nv_bfloat16* __restrict__ Vl,
              float* __restrict__ Of,
              __nv_bfloat16* __restrict__ Oh, __nv_bfloat16* __restrict__ Ol,
              int causal) {
    extern __shared__ char smc[];
    uint32_t sb = smem_u32(smc);
    const int tid = threadIdx.x;
    const int wid = tid >> 5, lane = tid & 31;
    const int q0 = blockIdx.x * 64;
    const int h = blockIdx.y, b = blockIdx.z;
    const size_t rowbase = (size_t)(b * SEQ);
    const int colbase = h * HDIM;

    const int lrow = (lane & 7) + ((lane >> 3) & 1) * 8;
    const int lkof = ((lane >> 4) & 1) * 8;
    const int vrow_l = (lane & 7) + ((lane >> 4) & 1) * 8;
    const int vcol_l = ((lane >> 3) & 1) * 8;

    attn_load_tile(sb + AQ_H, Qh + (rowbase + q0) * 1024 + colbase, tid);
    attn_load_tile(sb + AQ_L, Ql + (rowbase + q0) * 1024 + colbase, tid);
    attn_load_tile(sb + AST(0, 0), Kh + rowbase * 1024 + colbase, tid);
    attn_load_tile(sb + AST(0, 1), Kl + rowbase * 1024 + colbase, tid);
    attn_load_tile(sb + AST(0, 2), Vh + rowbase * 1024 + colbase, tid);
    attn_load_tile(sb + AST(0, 3), Vl + rowbase * 1024 + colbase, tid);
    CP_COMMIT();

    const int njt = causal ? (blockIdx.x + 1) : (SEQ / 64);

    uint32_t qhf[4][4], qlf[4][4];
    float o[8][4];
#pragma unroll
    for (int nt = 0; nt < 8; nt++)
#pragma unroll
        for (int q = 0; q < 4; q++) o[nt][q] = 0.f;
    float m_[2] = {-1e30f, -1e30f}, l_[2] = {0.f, 0.f};

    for (int j = 0; j < njt; j++) {
        CP_WAIT0();
        __syncthreads();
        if (j + 1 < njt) {
            const size_t kb = (rowbase + (size_t)(j + 1) * 64) * 1024 + colbase;
            const int s = (j + 1) & 1;
            attn_load_tile(sb + AST(s, 0), Kh + kb, tid);
            attn_load_tile(sb + AST(s, 1), Kl + kb, tid);
            attn_load_tile(sb + AST(s, 2), Vh + kb, tid);
            attn_load_tile(sb + AST(s, 3), Vl + kb, tid);
            CP_COMMIT();
        }
        if (j == 0) {
#pragma unroll
            for (int kt = 0; kt < 4; kt++) {
                uint32_t ro = (uint32_t)((wid * 16 + lrow) * 144 + (kt * 16 + lkof) * 2);
                LDSM_X4(qhf[kt][0], qhf[kt][1], qhf[kt][2], qhf[kt][3], sb + AQ_H + ro);
                LDSM_X4(qlf[kt][0], qlf[kt][1], qlf[kt][2], qlf[kt][3], sb + AQ_L + ro);
            }
        }

        const uint32_t khb = sb + AST(j & 1, 0);
        const uint32_t klb = sb + AST(j & 1, 1);
        const uint32_t vhb = sb + AST(j & 1, 2);
        const uint32_t vlb = sb + AST(j & 1, 3);

        float s[8][4];
#pragma unroll
        for (int nt = 0; nt < 8; nt++)
#pragma unroll
            for (int q = 0; q < 4; q++) s[nt][q] = 0.f;
#pragma unroll
        for (int kt = 0; kt < 4; kt++) {
            uint32_t bh[8][2], bl[8][2];
#pragma unroll
            for (int g = 0; g < 4; g++) {
                uint32_t ro = (uint32_t)((g * 16 + lrow) * 144 + (kt * 16 + lkof) * 2);
                uint32_t r0, r1, r2, r3;
                LDSM_X4(r0, r1, r2, r3, khb + ro);
                bh[2 * g + 0][0] = r0; bh[2 * g + 0][1] = r2;
                bh[2 * g + 1][0] = r1; bh[2 * g + 1][1] = r3;
                LDSM_X4(r0, r1, r2, r3, klb + ro);
                bl[2 * g + 0][0] = r0; bl[2 * g + 0][1] = r2;
                bl[2 * g + 1][0] = r1; bl[2 * g + 1][1] = r3;
            }
            // pass-outer ordering: 8 independent MMAs per pass
#pragma unroll
            for (int nt = 0; nt < 8; nt++)
                MMA_BF16(s[nt], qhf[kt], bh[nt][0], bh[nt][1]);
#pragma unroll
            for (int nt = 0; nt < 8; nt++)
                MMA_BF16(s[nt], qhf[kt], bl[nt][0], bl[nt][1]);
#pragma unroll
            for (int nt = 0; nt < 8; nt++)
                MMA_BF16(s[nt], qlf[kt], bh[nt][0], bh[nt][1]);
        }

#pragma unroll
        for (int nt = 0; nt < 8; nt++)
#pragma unroll
            for (int q = 0; q < 4; q++) s[nt][q] *= 0.125f;
        if (causal && j == njt - 1) {
            const int r0l = wid * 16 + (lane >> 2), r1l = r0l + 8;
#pragma unroll
            for (int nt = 0; nt < 8; nt++) {
                const int c0 = nt * 8 + (lane & 3) * 2;
                if (c0 > r0l)     s[nt][0] = -1e9f;
                if (c0 + 1 > r0l) s[nt][1] = -1e9f;
                if (c0 > r1l)     s[nt][2] = -1e9f;
                if (c0 + 1 > r1l) s[nt][3] = -1e9f;
            }
        }

        float mx0 = -1e30f, mx1 = -1e30f;
#pragma unroll
        for (int nt = 0; nt < 8; nt++) {
            mx0 = fmaxf(mx0, fmaxf(s[nt][0], s[nt][1]));
            mx1 = fmaxf(mx1, fmaxf(s[nt][2], s[nt][3]));
        }
        mx0 = fmaxf(mx0, __shfl_xor_sync(0xffffffffu, mx0, 1));
        mx0 = fmaxf(mx0, __shfl_xor_sync(0xffffffffu, mx0, 2));
        mx1 = fmaxf(mx1, __shfl_xor_sync(0xffffffffu, mx1, 1));
        mx1 = fmaxf(mx1, __shfl_xor_sync(0xffffffffu, mx1, 2));
        const float mn0 = fmaxf(m_[0], mx0), mn1 = fmaxf(m_[1], mx1);
        const float f0 = __expf(m_[0] - mn0), f1 = __expf(m_[1] - mn1);
        m_[0] = mn0; m_[1] = mn1;
        float rs0 = 0.f, rs1 = 0.f;
#pragma unroll
        for (int nt = 0; nt < 8; nt++) {
            s[nt][0] = __expf(s[nt][0] - mn0);
            s[nt][1] = __expf(s[nt][1] - mn0);
            s[nt][2] = __expf(s[nt][2] - mn1);
            s[nt][3] = __expf(s[nt][3] - mn1);
            rs0 += s[nt][0] + s[nt][1];
            rs1 += s[nt][2] + s[nt][3];
        }
        rs0 += __shfl_xor_sync(0xffffffffu, rs0, 1);
        rs0 += __shfl_xor_sync(0xffffffffu, rs0, 2);
        rs1 += __shfl_xor_sync(0xffffffffu, rs1, 1);
        rs1 += __shfl_xor_sync(0xffffffffu, rs1, 2);
        l_[0] = l_[0] * f0 + rs0;
        l_[1] = l_[1] * f1 + rs1;
#pragma unroll
        for (int nt = 0; nt < 8; nt++) {
            o[nt][0] *= f0; o[nt][1] *= f0; o[nt][2] *= f1; o[nt][3] *= f1;
        }

        uint32_t ph[4][4], pl[4][4];
#pragma unroll
        for (int kt = 0; kt < 4; kt++) {
            pack_split(s[2 * kt][0],     s[2 * kt][1],     ph[kt][0], pl[kt][0]);
            pack_split(s[2 * kt][2],     s[2 * kt][3],     ph[kt][1], pl[kt][1]);
            pack_split(s[2 * kt + 1][0], s[2 * kt + 1][1], ph[kt][2], pl[kt][2]);
            pack_split(s[2 * kt + 1][2], s[2 * kt + 1][3], ph[kt][3], pl[kt][3]);
        }

#pragma unroll
        for (int kt = 0; kt < 4; kt++) {
            const uint32_t vro = (uint32_t)((kt * 16 + vrow_l) * 144);
            uint32_t bh[8][2], bl[8][2];
#pragma unroll
            for (int g = 0; g < 4; g++) {
                uint32_t ro = vro + (uint32_t)((g * 16 + vcol_l) * 2);
                uint32_t r0, r1, r2, r3;
                LDSM_X4_T(r0, r1, r2, r3, vhb + ro);
                bh[2 * g + 0][0] = r0; bh[2 * g + 0][1] = r2;
                bh[2 * g + 1][0] = r1; bh[2 * g + 1][1] = r3;
                LDSM_X4_T(r0, r1, r2, r3, vlb + ro);
                bl[2 * g + 0][0] = r0; bl[2 * g + 0][1] = r2;
                bl[2 * g + 1][0] = r1; bl[2 * g + 1][1] = r3;
            }
#pragma unroll
            for (int nt = 0; nt < 8; nt++)
                MMA_BF16(o[nt], ph[kt], bh[nt][0], bh[nt][1]);
#pragma unroll
            for (int nt = 0; nt < 8; nt++)
                MMA_BF16(o[nt], ph[kt], bl[nt][0], bl[nt][1]);
#pragma unroll
            for (int nt = 0; nt < 8; nt++)
                MMA_BF16(o[nt], pl[kt], bh[nt][0], bh[nt][1]);
        }
    }

    const float inv0 = 1.f / l_[0], inv1 = 1.f / l_[1];
    const size_t row0 = rowbase + q0 + wid * 16 + (lane >> 2);
    const int col = colbase + (lane & 3) * 2;
    if (Of) {
#pragma unroll
        for (int nt = 0; nt < 8; nt++) {
            *(float2*)(Of + row0 * 1024 + col + nt * 8) =
                make_float2(o[nt][0] * inv0, o[nt][1] * inv0);
            *(float2*)(Of + (row0 + 8) * 1024 + col + nt * 8) =
                make_float2(o[nt][2] * inv1, o[nt][3] * inv1);
        }
    } else {
#pragma unroll
        for (int nt = 0; nt < 8; nt++) {
            uint32_t h01, l01, h23, l23;
            pack_split(o[nt][0] * inv0, o[nt][1] * inv0, h01, l01);
            pack_split(o[nt][2] * inv1, o[nt][3] * inv1, h23, l23);
            *(uint32_t*)(Oh + row0 * 1024 + col + nt * 8) = h01;
            *(uint32_t*)(Ol + row0 * 1024 + col + nt * 8) = l01;
            *(uint32_t*)(Oh + (row0 + 8) * 1024 + col + nt * 8) = h23;
            *(uint32_t*)(Ol + (row0 + 8) * 1024 + col + nt * 8) = l23;
        }
    }
}

// ================= launch =================
extern "C" void kernel_launch(void* const* d_in, const int* in_sizes, int n_in,
                              void* d_out, int out_size) {
    const float* x   = (const float*)d_in[0];
    const float* enc = (const float*)d_in[1];
    const float* w[6] = {(const float*)d_in[4], (const float*)d_in[5],
                         (const float*)d_in[6], (const float*)d_in[7],
                         (const float*)d_in[8], (const float*)d_in[9]};
    float* out = (float*)d_out;

    __nv_bfloat16 *qh, *ql, *kh, *kl, *vh, *vl, *ah, *al, *eh, *el, *wh, *wl;
    cudaGetSymbolAddress((void**)&qh, g_qh);
    cudaGetSymbolAddress((void**)&ql, g_ql);
    cudaGetSymbolAddress((void**)&kh, g_kh);
    cudaGetSymbolAddress((void**)&kl, g_kl);
    cudaGetSymbolAddress((void**)&vh, g_vh);
    cudaGetSymbolAddress((void**)&vl, g_vl);
    cudaGetSymbolAddress((void**)&ah, g_ah);
    cudaGetSymbolAddress((void**)&al, g_al);
    cudaGetSymbolAddress((void**)&eh, g_eh);
    cudaGetSymbolAddress((void**)&el, g_el);
    cudaGetSymbolAddress((void**)&wh, g_w6h);
    cudaGetSymbolAddress((void**)&wl, g_w6l);

    cudaFuncSetAttribute(gemm_qkv, cudaFuncAttributeMaxDynamicSharedMemorySize, GEMM_SMEM);
    cudaFuncSetAttribute(attn_mma, cudaFuncAttributeMaxDynamicSharedMemorySize, ATTN_SMEM);

    const size_t WSZ = (size_t)DMODEL * DMODEL;
    dim3 gg(DMODEL / BN, MTOT / BM, 3);                  // (8, 32, 3)
    dim3 ga(SEQ / 64, NHEAD, BATCH);                     // (16, 16, 4)

    // batched splits: acts (x, enc) and all 6 weights
    SplitBatch Sa = {};
    Sa.src[0] = x;   Sa.hi[0] = ah; Sa.lo[0] = al;
    Sa.src[1] = enc; Sa.hi[1] = eh; Sa.lo[1] = el;
    split_multi<<<dim3((MTOT * DMODEL) / (256 * 4), 2), 256>>>(Sa);

    SplitBatch Sw = {};
    for (int i = 0; i < 6; i++) {
        Sw.src[i] = w[i]; Sw.hi[i] = wh + i * WSZ; Sw.lo[i] = wl + i * WSZ;
    }
    split_multi<<<dim3((int)(WSZ / (256 * 4)), 6), 256>>>(Sw);

    // ---- self-attention block ----
    GemmTriple Ps;
    for (int zi = 0; zi < 3; zi++) {
        Ps.Ah[zi] = ah; Ps.Al[zi] = al;
        Ps.Bh[zi] = wh + zi * WSZ; Ps.Bl[zi] = wl + zi * WSZ;
    }
    Ps.Ch[0] = qh; Ps.Cl[0] = ql;
    Ps.Ch[1] = kh; Ps.Cl[1] = kl;
    Ps.Ch[2] = vh; Ps.Cl[2] = vl;
    gemm_qkv<<<gg, GT, GEMM_SMEM>>>(Ps);
    attn_mma<<<ga, 128, ATTN_SMEM>>>(qh, ql, kh, kl, vh, vl, nullptr, ah, al, 1);

    // ---- cross-attention block ----
    GemmTriple Pc;
    Pc.Ah[0] = ah; Pc.Al[0] = al;
    Pc.Ah[1] = eh; Pc.Al[1] = el;
    Pc.Ah[2] = eh; Pc.Al[2] = el;
    for (int zi = 0; zi < 3; zi++) {
        Pc.Bh[zi] = wh + (3 + zi) * WSZ; Pc.Bl[zi] = wl + (3 + zi) * WSZ;
    }
    Pc.Ch[0] = qh; Pc.Cl[0] = ql;
    Pc.Ch[1] = kh; Pc.Cl[1] = kl;
    Pc.Ch[2] = vh; Pc.Cl[2] = vl;
    gemm_qkv<<<gg, GT, GEMM_SMEM>>>(Pc);
    attn_mma<<<ga, 128, ATTN_SMEM>>>(qh, ql, kh, kl, vh, vl, out, nullptr, nullptr, 0);
}